// round 14
// baseline (speedup 1.0000x reference)
#include <cuda_runtime.h>
#include <cuda_fp16.h>
#include <math.h>

#define B_ 32
#define T_ 64
#define N_ 32
#define D_ 128
#define E_ 8
#define K_ 2

typedef unsigned long long u64;
typedef unsigned int u32;

// SMEM u32-unit offsets
#define OFF_XA  0        // x     [64][68]  half2 (d-pairs)
#define OFF_KS  4352     // K     [64][68]  half2 (dc-pairs)
#define OFF_VT  8704     // V^T   [128][36] half2 (t-pairs)
#define OFF_PS  13312    // P     [2][64][36] half2 (kt-pairs)
#define OFF_OS  17920    // O     [64][68]  half2   (S overlays OS+O1)
#define OFF_O1  22272    // O1    [64][68]  half2
#define OFF_WS  26624    // buffer A: 20480 u32 (80KB)
#define OFF_WSB 47104    // buffer B: 10240 u32 (40KB)
#define SMEM_U  57344    // *4 = 229376 bytes

__device__ int   d_eidx[B_][K_];
__device__ float d_gateg[B_][K_];
__device__ float d_part[B_][64][D_];

// Pre-converted fp16 weights in staging layout
__device__ u32 WdT_g[8 * 32 * 4 * 5120];   // ~21 MB
__device__ u32 WsT_g[16 * 4 * 2560];       // 640 KB

__device__ __forceinline__ u64 fpack(float lo, float hi) {
    u64 d; asm("mov.b64 %0, {%1, %2};" : "=l"(d) : "f"(lo), "f"(hi)); return d;
}
__device__ __forceinline__ u32 h2pack(float lo, float hi) {
    __half2 h = __floats2half2_rn(lo, hi);
    return *(u32*)&h;
}
__device__ __forceinline__ void mma_f16(float* c, const u32* a, const u32* b) {
    asm volatile(
        "mma.sync.aligned.m16n8k16.row.col.f32.f16.f16.f32 "
        "{%0,%1,%2,%3}, {%4,%5,%6,%7}, {%8,%9}, {%0,%1,%2,%3};\n"
        : "+f"(c[0]), "+f"(c[1]), "+f"(c[2]), "+f"(c[3])
        : "r"(a[0]), "r"(a[1]), "r"(a[2]), "r"(a[3]), "r"(b[0]), "r"(b[1]));
}
__device__ __forceinline__ void cp16(u32 smem_addr, const void* gptr) {
    asm volatile("cp.async.cg.shared.global [%0], [%1], 16;" :: "r"(smem_addr), "l"(gptr));
}
#define CP_COMMIT() asm volatile("cp.async.commit_group;")
#define CP_WAIT0()  asm volatile("cp.async.wait_group 0;")

// ---------------------------------------------------------------------------
// Fused prep (weight convert) + gate_partial (x row sums). 3136 CTAs.
// ---------------------------------------------------------------------------
__global__ void prep_gate_kernel(const float* __restrict__ Wd,
                                 const float* __restrict__ Ws,
                                 const float* __restrict__ x) {
    __shared__ float tile[32][129];
    const int bid = blockIdx.x;
    const int tid = threadIdx.x;   // 256
    if (bid < 2112) {
        const float* src;
        u32* dst;
        if (bid < 2048) {
            const int s = bid & 3, mat = (bid >> 2) & 1, n = (bid >> 3) & 31, e = bid >> 8;
            src = Wd + ((size_t)(e * 2 + mat) * 32 + n) * (128 * 128) + s * 32 * 128;
            dst = WdT_g + ((size_t)((e * 32 + n) * 4 + s)) * 5120 + mat * 2560;
        } else {
            const int r = bid - 2048;
            const int s = r & 3, em = r >> 2;
            src = Ws + (size_t)em * (128 * 128) + s * 32 * 128;
            dst = WsT_g + ((size_t)em * 4 + s) * 2560;
        }
        #pragma unroll
        for (int i = tid; i < 4096; i += 256)
            tile[i >> 7][i & 127] = src[i];
        __syncthreads();
        for (int j = tid; j < 2560; j += 256) {
            const int c = j / 20, d2 = j % 20;
            u32 v = 0;
            if (d2 < 16) v = h2pack(tile[2 * d2][c], tile[2 * d2 + 1][c]);
            dst[j] = v;
        }
    } else {
        const int r    = bid - 2112;        // 0..1023
        const int b    = r >> 5, ch = r & 31;
        const int sub  = tid >> 7;          // 0/1
        const int lane = tid & 127;
        const float* base = x + ((size_t)b * T_ * N_ + ch * 64 + sub * 32) * D_;
        float s = 0.f;
        #pragma unroll 8
        for (int rr = 0; rr < 32; ++rr) s += base[rr * D_ + lane];
        d_part[b][ch * 2 + sub][lane] = s;
    }
}

// ---------------------------------------------------------------------------
// Gating stage 2
// ---------------------------------------------------------------------------
__global__ void gate_kernel(const float* __restrict__ Wg) {
    const int b   = blockIdx.x;
    const int tid = threadIdx.x;   // 128
    __shared__ float smean[D_];
    __shared__ float slog[E_];

    float s = 0.f;
    #pragma unroll
    for (int c = 0; c < 64; ++c) s += d_part[b][c][tid];
    smean[tid] = s * (1.0f / (float)(T_ * N_));
    __syncthreads();

    if (tid < E_) {
        float l = 0.f;
        for (int d = 0; d < D_; ++d) l += smean[d] * Wg[d * E_ + tid];
        slog[tid] = l;
    }
    __syncthreads();

    if (tid == 0) {
        int i0 = 0; float v0 = slog[0];
        for (int e = 1; e < E_; ++e) if (slog[e] > v0) { v0 = slog[e]; i0 = e; }
        int i1 = -1; float v1 = -3.0e38f;
        for (int e = 0; e < E_; ++e) if (e != i0 && slog[e] > v1) { v1 = slog[e]; i1 = e; }
        const float e1  = expf(v1 - v0);
        const float inv = 1.0f / (1.0f + e1);
        d_eidx[b][0]  = i0; d_eidx[b][1]  = i1;
        d_gateg[b][0] = inv; d_gateg[b][1] = e1 * inv;
    }
}

// ---------------------------------------------------------------------------
// Kernel 2: fp16 mma; dual weight buffers A(80K)+B(40K); every weight
// staging overlapped with compute.
// ---------------------------------------------------------------------------
__global__ __launch_bounds__(512, 1)
void moe_kernel(const float* __restrict__ x,
                const float* __restrict__ bd,
                const float* __restrict__ bs,
                float* __restrict__ out) {
    extern __shared__ u32 smu[];
    u32*   XA  = smu + OFF_XA;
    u32*   KS  = smu + OFF_KS;
    u32*   VT  = smu + OFF_VT;
    u32*   PS  = smu + OFF_PS;
    u32*   OS  = smu + OFF_OS;
    u32*   O1  = smu + OFF_O1;
    u32*   WS  = smu + OFF_WS;
    u32*   WSB = smu + OFF_WSB;
    float* S   = (float*)(smu + OFF_OS);

    const u32 ws_s  = (u32)__cvta_generic_to_shared(WS);
    const u32 wsb_s = (u32)__cvta_generic_to_shared(WSB);

    const int n    = blockIdx.x;
    const int b    = blockIdx.y;
    const int tid  = threadIdx.x;
    const int lane = tid & 31;
    const int wid  = tid >> 5;
    const int g    = lane >> 2;
    const int tq   = lane & 3;

    // mappings
    const int matId = wid >> 3;
    const int k_m0  = (wid & 3) * 16;
    const int k_n0  = ((wid >> 2) & 1) * 64;
    const int v_m0  = (wid & 7) * 16;
    const int h     = wid >> 3;
    const int a_m0  = (wid & 3) * 16;
    const int a_n0  = ((wid >> 2) & 1) * 32;
    const int g2_m0 = (wid & 3) * 16;
    const int g2_n0 = (wid >> 2) * 32;

    // G0: stage Wd(e0) -> A (overlaps x load)
    {
        const int e0 = d_eidx[b][0];
        const u32* wdsrc = WdT_g + ((size_t)(e0 * 32 + n) * 4) * 5120;
        #pragma unroll
        for (int j = tid; j < 5120; j += 512)
            cp16(ws_s + (u32)(j * 16), wdsrc + j * 4);
        CP_COMMIT();
    }

    // ---- load x -> XA half2 ----
    {
        const float4* xg = (const float4*)(x + ((size_t)b * T_ * N_ + n) * D_);
        #pragma unroll
        for (int i = tid; i < T_ * D_ / 4; i += 512) {
            const int t  = i >> 5;
            const int c2 = (i & 31) * 2;
            float4 v = xg[(size_t)t * (N_ * D_ / 4) + (i & 31)];
            XA[t * 68 + c2]     = h2pack(v.x, v.y);
            XA[t * 68 + c2 + 1] = h2pack(v.z, v.w);
        }
    }

    float accv[4][4];
    #pragma unroll
    for (int ni = 0; ni < 4; ++ni)
        #pragma unroll
        for (int c = 0; c < 4; ++c) accv[ni][c] = 0.f;

    #pragma unroll
    for (int slot = 0; slot < K_; ++slot) {
        const int   e  = d_eidx[b][slot];
        const float gg = d_gateg[b][slot];

        // wait pending weight staging (G0 for slot0, G2 for slot1) + XA stores
        CP_WAIT0();
        __syncthreads();

        // =================== GEMM1: K = x@W0+b0 ; V^T = W1^T@x^T + b1 ===================
        {
            float acc[8][4];
            if (matId == 0) {
                const float* bm = bd + ((size_t)(e * 2 + 0) * N_ + n) * D_;
                #pragma unroll
                for (int ni = 0; ni < 8; ++ni) {
                    const float b0v = bm[k_n0 + 8 * ni + 2 * tq];
                    const float b1v = bm[k_n0 + 8 * ni + 2 * tq + 1];
                    acc[ni][0] = b0v; acc[ni][1] = b1v; acc[ni][2] = b0v; acc[ni][3] = b1v;
                }
            } else {
                const float* bm = bd + ((size_t)(e * 2 + 1) * N_ + n) * D_;
                const float blo = bm[v_m0 + g];
                const float bhi = bm[v_m0 + 8 + g];
                #pragma unroll
                for (int ni = 0; ni < 8; ++ni) {
                    acc[ni][0] = blo; acc[ni][1] = blo; acc[ni][2] = bhi; acc[ni][3] = bhi;
                }
            }
            #pragma unroll
            for (int s = 0; s < 4; ++s) {
                // slot0: Wd in A slabs 0-3; slot1: s01 in A_hi, s23 in B
                const u32* cur = (slot == 0) ? (WS + s * 5120)
                               : ((s < 2) ? (WS + 10240 + s * 5120)
                                          : (WSB + (s - 2) * 5120));
                #pragma unroll
                for (int kk = 0; kk < 2; ++kk) {
                    const int d2g = s * 16 + kk * 8;
                    if (matId == 0) {
                        u32 a[4];
                        a[0] = XA[(k_m0 + g)     * 68 + d2g + tq];
                        a[1] = XA[(k_m0 + 8 + g) * 68 + d2g + tq];
                        a[2] = XA[(k_m0 + g)     * 68 + d2g + tq + 4];
                        a[3] = XA[(k_m0 + 8 + g) * 68 + d2g + tq + 4];
                        #pragma unroll
                        for (int ni = 0; ni < 8; ++ni) {
                            u32 bf[2];
                            bf[0] = cur[(k_n0 + 8 * ni + g) * 20 + kk * 8 + tq];
                            bf[1] = cur[(k_n0 + 8 * ni + g) * 20 + kk * 8 + tq + 4];
                            mma_f16(acc[ni], a, bf);
                        }
                    } else {
                        u32 a[4];
                        a[0] = cur[2560 + (v_m0 + g)     * 20 + kk * 8 + tq];
                        a[1] = cur[2560 + (v_m0 + 8 + g) * 20 + kk * 8 + tq];
                        a[2] = cur[2560 + (v_m0 + g)     * 20 + kk * 8 + tq + 4];
                        a[3] = cur[2560 + (v_m0 + 8 + g) * 20 + kk * 8 + tq + 4];
                        #pragma unroll
                        for (int ni = 0; ni < 8; ++ni) {
                            u32 bf[2];
                            bf[0] = XA[(8 * ni + g) * 68 + d2g + tq];
                            bf[1] = XA[(8 * ni + g) * 68 + d2g + tq + 4];
                            mma_f16(acc[ni], a, bf);
                        }
                    }
                }
            }
            if (matId == 0) {
                #pragma unroll
                for (int ni = 0; ni < 8; ++ni) {
                    KS[(k_m0 + g)     * 68 + k_n0 / 2 + 4 * ni + tq] = h2pack(acc[ni][0], acc[ni][1]);
                    KS[(k_m0 + 8 + g) * 68 + k_n0 / 2 + 4 * ni + tq] = h2pack(acc[ni][2], acc[ni][3]);
                }
            } else {
                #pragma unroll
                for (int ni = 0; ni < 8; ++ni) {
                    VT[(v_m0 + g)     * 36 + 4 * ni + tq] = h2pack(acc[ni][0], acc[ni][1]);
                    VT[(v_m0 + 8 + g) * 36 + 4 * ni + tq] = h2pack(acc[ni][2], acc[ni][3]);
                }
            }
            __syncthreads();
        }

        // G1/G3: stage Ws(e). slot0: Ws0->B, Ws1->A_lo; slot1: Ws0->A_lo, Ws1->A_hi.
        // Hidden behind att + softmax + PV.
        {
            const u32* s0 = WsT_g + (size_t)(e * 2) * 4 * 2560;       // Ws0 (10240 u32)
            const u32* s1 = s0 + 10240;                                // Ws1
            if (slot == 0) {
                #pragma unroll
                for (int j = tid; j < 2560; j += 512) {
                    cp16(wsb_s + (u32)(j * 16), s0 + j * 4);
                    cp16(ws_s  + (u32)(j * 16), s1 + j * 4);
                }
            } else {
                #pragma unroll
                for (int j = tid; j < 2560; j += 512) {
                    cp16(ws_s + (u32)(j * 16),         s0 + j * 4);
                    cp16(ws_s + 40960u + (u32)(j * 16), s1 + j * 4);
                }
            }
            CP_COMMIT();
        }

        // =================== att: S = Q K^T / 8 (per head) ===================
        {
            const int hb2 = h * 32;
            float sa[4][4];
            #pragma unroll
            for (int ni = 0; ni < 4; ++ni)
                #pragma unroll
                for (int c = 0; c < 4; ++c) sa[ni][c] = 0.f;
            #pragma unroll
            for (int ks = 0; ks < 4; ++ks) {
                const int d2g = hb2 + ks * 8;
                u32 a[4];
                a[0] = XA[(a_m0 + g)     * 68 + d2g + tq];
                a[1] = XA[(a_m0 + 8 + g) * 68 + d2g + tq];
                a[2] = XA[(a_m0 + g)     * 68 + d2g + tq + 4];
                a[3] = XA[(a_m0 + 8 + g) * 68 + d2g + tq + 4];
                #pragma unroll
                for (int ni = 0; ni < 4; ++ni) {
                    u32 bf[2];
                    bf[0] = KS[(a_n0 + 8 * ni + g) * 68 + d2g + tq];
                    bf[1] = KS[(a_n0 + 8 * ni + g) * 68 + d2g + tq + 4];
                    mma_f16(sa[ni], a, bf);
                }
            }
            float* Sh = S + h * 4352;
            #pragma unroll
            for (int ni = 0; ni < 4; ++ni) {
                const int cc = a_n0 + 8 * ni + 2 * tq;
                *(u64*)&Sh[(a_m0 + g)     * 68 + cc] = fpack(0.125f * sa[ni][0], 0.125f * sa[ni][1]);
                *(u64*)&Sh[(a_m0 + 8 + g) * 68 + cc] = fpack(0.125f * sa[ni][2], 0.125f * sa[ni][3]);
            }
            __syncthreads();
        }

        // =================== softmax -> P (half) ===================
        {
            __half* Pb = (__half*)PS;
            #pragma unroll
            for (int j = 0; j < 8; ++j) {
                const int r  = wid * 8 + j;
                const int hh = r >> 6;
                const int t  = r & 63;
                float* row = S + hh * 4352 + t * 68;
                const float a0 = row[lane];
                const float a1 = row[lane + 32];
                float m = fmaxf(a0, a1);
                #pragma unroll
                for (int o = 16; o > 0; o >>= 1) m = fmaxf(m, __shfl_xor_sync(0xffffffffu, m, o));
                const float e0 = __expf(a0 - m);
                const float e1 = __expf(a1 - m);
                float sum = e0 + e1;
                #pragma unroll
                for (int o = 16; o > 0; o >>= 1) sum += __shfl_xor_sync(0xffffffffu, sum, o);
                const float inv = 1.0f / sum;
                __half* Ph = Pb + hh * 4608 + t * 72;
                Ph[lane]      = __float2half_rn(e0 * inv);
                Ph[lane + 32] = __float2half_rn(e1 * inv);
            }
            __syncthreads();
        }

        // =================== O = P V (per head) ===================
        {
            const u32* Pu = PS + h * 2304;
            float oa[4][4];
            #pragma unroll
            for (int ni = 0; ni < 4; ++ni)
                #pragma unroll
                for (int c = 0; c < 4; ++c) oa[ni][c] = 0.f;
            #pragma unroll
            for (int ks = 0; ks < 4; ++ks) {
                const int kt2 = ks * 8;
                u32 a[4];
                a[0] = Pu[(a_m0 + g)     * 36 + kt2 + tq];
                a[1] = Pu[(a_m0 + 8 + g) * 36 + kt2 + tq];
                a[2] = Pu[(a_m0 + g)     * 36 + kt2 + tq + 4];
                a[3] = Pu[(a_m0 + 8 + g) * 36 + kt2 + tq + 4];
                #pragma unroll
                for (int ni = 0; ni < 4; ++ni) {
                    u32 bf[2];
                    bf[0] = VT[(h * 64 + a_n0 + 8 * ni + g) * 36 + kt2 + tq];
                    bf[1] = VT[(h * 64 + a_n0 + 8 * ni + g) * 36 + kt2 + tq + 4];
                    mma_f16(oa[ni], a, bf);
                }
            }
            #pragma unroll
            for (int ni = 0; ni < 4; ++ni) {
                const int c2 = h * 32 + a_n0 / 2 + 4 * ni + tq;
                OS[(a_m0 + g)     * 68 + c2] = h2pack(oa[ni][0], oa[ni][1]);
                OS[(a_m0 + 8 + g) * 68 + c2] = h2pack(oa[ni][2], oa[ni][3]);
            }
            CP_WAIT0();        // Ws staging complete
            __syncthreads();   // OS stores + Ws visible to all
        }

        // =================== GEMM2: O1 = relu(O @ Ws0 + bs0) ===================
        {
            const u32* w2 = (slot == 0) ? WSB : WS;   // Ws0
            const float* bsp = bs + (e * 2 + 0) * D_;
            float acc[4][4];
            #pragma unroll
            for (int ni = 0; ni < 4; ++ni) {
                const float b0v = bsp[g2_n0 + 8 * ni + 2 * tq];
                const float b1v = bsp[g2_n0 + 8 * ni + 2 * tq + 1];
                acc[ni][0] = b0v; acc[ni][1] = b1v; acc[ni][2] = b0v; acc[ni][3] = b1v;
            }
            #pragma unroll
            for (int s = 0; s < 4; ++s) {
                const u32* cur = w2 + s * 2560;
                #pragma unroll
                for (int kk = 0; kk < 2; ++kk) {
                    const int d2g = s * 16 + kk * 8;
                    u32 a[4];
                    a[0] = OS[(g2_m0 + g)     * 68 + d2g + tq];
                    a[1] = OS[(g2_m0 + 8 + g) * 68 + d2g + tq];
                    a[2] = OS[(g2_m0 + g)     * 68 + d2g + tq + 4];
                    a[3] = OS[(g2_m0 + 8 + g) * 68 + d2g + tq + 4];
                    #pragma unroll
                    for (int ni = 0; ni < 4; ++ni) {
                        u32 bf[2];
                        bf[0] = cur[(g2_n0 + 8 * ni + g) * 20 + kk * 8 + tq];
                        bf[1] = cur[(g2_n0 + 8 * ni + g) * 20 + kk * 8 + tq + 4];
                        mma_f16(acc[ni], a, bf);
                    }
                }
            }
            #pragma unroll
            for (int ni = 0; ni < 4; ++ni) {
                const int c2 = g2_n0 / 2 + 4 * ni + tq;
                O1[(g2_m0 + g)     * 68 + c2] = h2pack(fmaxf(acc[ni][0], 0.f), fmaxf(acc[ni][1], 0.f));
                O1[(g2_m0 + 8 + g) * 68 + c2] = h2pack(fmaxf(acc[ni][2], 0.f), fmaxf(acc[ni][3], 0.f));
            }
            __syncthreads();
        }

        // G2: stage Wd(e1) {s01 -> A_hi, s23 -> B} — hidden behind GEMM3
        if (slot == 0) {
            const int e1 = d_eidx[b][1];
            const u32* wd1 = WdT_g + ((size_t)(e1 * 32 + n) * 4) * 5120;
            #pragma unroll
            for (int j = tid; j < 2560; j += 512) {
                cp16(ws_s + 40960u + (u32)(j * 16), wd1 + j * 4);
                cp16(wsb_s + (u32)(j * 16), wd1 + 10240 + j * 4);
            }
            CP_COMMIT();
        }

        // =================== GEMM3: out_e = O1 @ Ws1 + bs1 ; accv += g*exp ===================
        {
            const u32* w3 = (slot == 0) ? WS : (WS + 10240);   // Ws1
            const float* bsp = bs + (e * 2 + 1) * D_;
            float acc[4][4];
            #pragma unroll
            for (int ni = 0; ni < 4; ++ni) {
                const float b0v = bsp[g2_n0 + 8 * ni + 2 * tq];
                const float b1v = bsp[g2_n0 + 8 * ni + 2 * tq + 1];
                acc[ni][0] = b0v; acc[ni][1] = b1v; acc[ni][2] = b0v; acc[ni][3] = b1v;
            }
            #pragma unroll
            for (int s = 0; s < 4; ++s) {
                const u32* cur = w3 + s * 2560;
                #pragma unroll
                for (int kk = 0; kk < 2; ++kk) {
                    const int d2g = s * 16 + kk * 8;
                    u32 a[4];
                    a[0] = O1[(g2_m0 + g)     * 68 + d2g + tq];
                    a[1] = O1[(g2_m0 + 8 + g) * 68 + d2g + tq];
                    a[2] = O1[(g2_m0 + g)     * 68 + d2g + tq + 4];
                    a[3] = O1[(g2_m0 + 8 + g) * 68 + d2g + tq + 4];
                    #pragma unroll
                    for (int ni = 0; ni < 4; ++ni) {
                        u32 bf[2];
                        bf[0] = cur[(g2_n0 + 8 * ni + g) * 20 + kk * 8 + tq];
                        bf[1] = cur[(g2_n0 + 8 * ni + g) * 20 + kk * 8 + tq + 4];
                        mma_f16(acc[ni], a, bf);
                    }
                }
            }
            #pragma unroll
            for (int ni = 0; ni < 4; ++ni)
                #pragma unroll
                for (int c = 0; c < 4; ++c)
                    accv[ni][c] += gg * __expf(acc[ni][c]);
        }
        // no end-of-loop barrier: next-slot top CP_WAIT0 + __syncthreads covers ordering
    }

    // ---- combine epilogue ----
    const float EPSF = 2.2204460492503131e-16f;
    #pragma unroll
    for (int ni = 0; ni < 4; ++ni) {
        const int cc  = g2_n0 + 8 * ni + 2 * tq;
        const int t0r = g2_m0 + g;
        const int t1r = g2_m0 + 8 + g;
        float v0 = accv[ni][0]; if (v0 == 0.f) v0 = EPSF;
        float v1 = accv[ni][1]; if (v1 == 0.f) v1 = EPSF;
        float v2 = accv[ni][2]; if (v2 == 0.f) v2 = EPSF;
        float v3 = accv[ni][3]; if (v3 == 0.f) v3 = EPSF;
        *(u64*)&out[(((size_t)b * T_ + t0r) * N_ + n) * D_ + cc] = fpack(__logf(v0), __logf(v1));
        *(u64*)&out[(((size_t)b * T_ + t1r) * N_ + n) * D_ + cc] = fpack(__logf(v2), __logf(v3));
    }
}

// ---------------------------------------------------------------------------
// launcher
// ---------------------------------------------------------------------------
extern "C" void kernel_launch(void* const* d_in, const int* in_sizes, int n_in,
                              void* d_out, int out_size) {
    const float* x  = (const float*)d_in[0];
    const float* Wg = (const float*)d_in[1];
    const float* Wd = (const float*)d_in[2];
    const float* bd = (const float*)d_in[3];
    const float* Ws = (const float*)d_in[4];
    const float* bs = (const float*)d_in[5];
    float* out = (float*)d_out;

    const int smem_bytes = SMEM_U * 4; // 229376 B
    cudaFuncSetAttribute(moe_kernel, cudaFuncAttributeMaxDynamicSharedMemorySize, smem_bytes);

    prep_gate_kernel<<<3136, 256>>>(Wd, Ws, x);
    gate_kernel<<<B_, 128>>>(Wg);
    dim3 grid(N_, B_);
    moe_kernel<<<grid, 512, smem_bytes>>>(x, bd, bs, out);
}

// round 15
// speedup vs baseline: 1.0526x; 1.0526x over previous
#include <cuda_runtime.h>
#include <cuda_fp16.h>
#include <math.h>

#define B_ 32
#define T_ 64
#define N_ 32
#define D_ 128
#define E_ 8
#define K_ 2

typedef unsigned long long u64;
typedef unsigned int u32;

// SMEM u32-unit offsets
#define OFF_XA  0        // x     [64][68]  half2 (d-pairs)
#define OFF_KS  4352     // K     [64][68]  half2 (dc-pairs)
#define OFF_VT  8704     // V^T   [128][36] half2 (t-pairs)
#define OFF_PS  13312    // P     [2][64][36] half2 (kt-pairs)
#define OFF_OS  17920    // O     [64][68]  half2   (S overlays OS+O1)
#define OFF_O1  22272    // O1    [64][68]  half2
#define OFF_WS  26624    // weight buffer: 17408 u32 (68KB)
#define SMEM_U  44032    // *4 = 176128 bytes

// weight slab layout: [d2][c] stride 136 (16 rows x 128 cols + 8 pad)
#define WSLAB   2176     // u32 per matrix slab
#define WBLK    4352     // u32 per (mat0+mat1) slab pair
#define WDEXP   17408    // u32 per (e,n) full Wd  (= Ws0+Ws1 total too)

__device__ int   d_eidx[B_][K_];
__device__ float d_gateg[B_][K_];
__device__ float d_part[B_][64][D_];

// Pre-converted fp16 weights: [d2][c]-major, stride 136
__device__ u32 WdT_g[8 * 32 * WDEXP];      // ~17 MB
__device__ u32 WsT_g[16 * 4 * WSLAB];      // 545 KB

__device__ __forceinline__ u64 fpack(float lo, float hi) {
    u64 d; asm("mov.b64 %0, {%1, %2};" : "=l"(d) : "f"(lo), "f"(hi)); return d;
}
__device__ __forceinline__ u32 h2pack(float lo, float hi) {
    __half2 h = __floats2half2_rn(lo, hi);
    return *(u32*)&h;
}
__device__ __forceinline__ void mma_f16(float* c, const u32* a, const u32* b) {
    asm volatile(
        "mma.sync.aligned.m16n8k16.row.col.f32.f16.f16.f32 "
        "{%0,%1,%2,%3}, {%4,%5,%6,%7}, {%8,%9}, {%0,%1,%2,%3};\n"
        : "+f"(c[0]), "+f"(c[1]), "+f"(c[2]), "+f"(c[3])
        : "r"(a[0]), "r"(a[1]), "r"(a[2]), "r"(a[3]), "r"(b[0]), "r"(b[1]));
}
__device__ __forceinline__ void cp16(u32 smem_addr, const void* gptr) {
    asm volatile("cp.async.cg.shared.global [%0], [%1], 16;" :: "r"(smem_addr), "l"(gptr));
}
#define CP_COMMIT() asm volatile("cp.async.commit_group;")
#define CP_WAIT0()  asm volatile("cp.async.wait_group 0;")

// ---------------------------------------------------------------------------
// Fused prep (transpose-free weight convert) + gate_partial. 3136 CTAs.
// ---------------------------------------------------------------------------
__global__ void prep_gate_kernel(const float* __restrict__ Wd,
                                 const float* __restrict__ Ws,
                                 const float* __restrict__ x) {
    const int bid = blockIdx.x;
    const int tid = threadIdx.x;   // 256
    if (bid < 2112) {
        const float* src;
        u32* dst;
        if (bid < 2048) {
            const int s = bid & 3, mat = (bid >> 2) & 1, n = (bid >> 3) & 31, e = bid >> 8;
            src = Wd + ((size_t)(e * 2 + mat) * 32 + n) * (128 * 128) + s * 32 * 128;
            dst = WdT_g + ((size_t)(e * 32 + n)) * WDEXP + s * WBLK + mat * WSLAB;
        } else {
            const int r = bid - 2048;
            const int s = r & 3, em = r >> 2;
            src = Ws + (size_t)em * (128 * 128) + s * 32 * 128;
            dst = WsT_g + ((size_t)em * 4 + s) * WSLAB;
        }
        // thread j -> (d2 = j>>7, c = j&127): coalesced reads AND writes
        #pragma unroll
        for (int j = tid; j < 2048; j += 256) {
            const int d2 = j >> 7, c = j & 127;
            dst[d2 * 136 + c] = h2pack(src[(2 * d2) * 128 + c],
                                       src[(2 * d2 + 1) * 128 + c]);
        }
    } else {
        const int r    = bid - 2112;        // 0..1023
        const int b    = r >> 5, ch = r & 31;
        const int sub  = tid >> 7;          // 0/1
        const int lane = tid & 127;
        const float* base = x + ((size_t)b * T_ * N_ + ch * 64 + sub * 32) * D_;
        float s = 0.f;
        #pragma unroll 8
        for (int rr = 0; rr < 32; ++rr) s += base[rr * D_ + lane];
        d_part[b][ch * 2 + sub][lane] = s;
    }
}

// ---------------------------------------------------------------------------
// Gating stage 2
// ---------------------------------------------------------------------------
__global__ void gate_kernel(const float* __restrict__ Wg) {
    const int b   = blockIdx.x;
    const int tid = threadIdx.x;   // 128
    __shared__ float smean[D_];
    __shared__ float slog[E_];

    float s = 0.f;
    #pragma unroll
    for (int c = 0; c < 64; ++c) s += d_part[b][c][tid];
    smean[tid] = s * (1.0f / (float)(T_ * N_));
    __syncthreads();

    if (tid < E_) {
        float l = 0.f;
        for (int d = 0; d < D_; ++d) l += smean[d] * Wg[d * E_ + tid];
        slog[tid] = l;
    }
    __syncthreads();

    if (tid == 0) {
        int i0 = 0; float v0 = slog[0];
        for (int e = 1; e < E_; ++e) if (slog[e] > v0) { v0 = slog[e]; i0 = e; }
        int i1 = -1; float v1 = -3.0e38f;
        for (int e = 0; e < E_; ++e) if (e != i0 && slog[e] > v1) { v1 = slog[e]; i1 = e; }
        const float e1  = expf(v1 - v0);
        const float inv = 1.0f / (1.0f + e1);
        d_eidx[b][0]  = i0; d_eidx[b][1]  = i1;
        d_gateg[b][0] = inv; d_gateg[b][1] = e1 * inv;
    }
}

// ---------------------------------------------------------------------------
// Kernel 2: fp16 mma (R13 schedule), [d2][c]-major weight slabs (stride 136)
// ---------------------------------------------------------------------------
__global__ __launch_bounds__(512, 1)
void moe_kernel(const float* __restrict__ x,
                const float* __restrict__ bd,
                const float* __restrict__ bs,
                float* __restrict__ out) {
    extern __shared__ u32 smu[];
    u32*   XA = smu + OFF_XA;
    u32*   KS = smu + OFF_KS;
    u32*   VT = smu + OFF_VT;
    u32*   PS = smu + OFF_PS;
    u32*   OS = smu + OFF_OS;
    u32*   O1 = smu + OFF_O1;
    u32*   WS = smu + OFF_WS;
    float* S  = (float*)(smu + OFF_OS);

    const u32 ws_s = (u32)__cvta_generic_to_shared(WS);

    const int n    = blockIdx.x;
    const int b    = blockIdx.y;
    const int tid  = threadIdx.x;
    const int lane = tid & 31;
    const int wid  = tid >> 5;
    const int g    = lane >> 2;
    const int tq   = lane & 3;

    // mappings
    const int matId = wid >> 3;
    const int k_m0  = (wid & 3) * 16;
    const int k_n0  = ((wid >> 2) & 1) * 64;
    const int v_m0  = (wid & 7) * 16;
    const int h     = wid >> 3;
    const int a_m0  = (wid & 3) * 16;
    const int a_n0  = ((wid >> 2) & 1) * 32;
    const int g2_m0 = (wid & 3) * 16;
    const int g2_n0 = (wid >> 2) * 32;

    // stage Wd(e0) -> WS (overlaps x load)
    {
        const int e0 = d_eidx[b][0];
        const u32* wdsrc = WdT_g + (size_t)(e0 * 32 + n) * WDEXP;
        #pragma unroll
        for (int j = tid; j < WDEXP / 4; j += 512)
            cp16(ws_s + (u32)(j * 16), wdsrc + j * 4);
        CP_COMMIT();
    }

    // ---- load x -> XA half2 ----
    {
        const float4* xg = (const float4*)(x + ((size_t)b * T_ * N_ + n) * D_);
        #pragma unroll
        for (int i = tid; i < T_ * D_ / 4; i += 512) {
            const int t  = i >> 5;
            const int c2 = (i & 31) * 2;
            float4 v = xg[(size_t)t * (N_ * D_ / 4) + (i & 31)];
            XA[t * 68 + c2]     = h2pack(v.x, v.y);
            XA[t * 68 + c2 + 1] = h2pack(v.z, v.w);
        }
    }

    float accv[4][4];
    #pragma unroll
    for (int ni = 0; ni < 4; ++ni)
        #pragma unroll
        for (int c = 0; c < 4; ++c) accv[ni][c] = 0.f;

    for (int slot = 0; slot < K_; ++slot) {
        const int   e  = d_eidx[b][slot];
        const float gg = d_gateg[b][slot];

        // wait for Wd staging (+ XA stores on slot 0)
        CP_WAIT0();
        __syncthreads();

        // =================== GEMM1: K = x@W0+b0 ; V^T = W1^T@x^T + b1 ===================
        {
            float acc[8][4];
            if (matId == 0) {
                const float* bm = bd + ((size_t)(e * 2 + 0) * N_ + n) * D_;
                #pragma unroll
                for (int ni = 0; ni < 8; ++ni) {
                    const float b0v = bm[k_n0 + 8 * ni + 2 * tq];
                    const float b1v = bm[k_n0 + 8 * ni + 2 * tq + 1];
                    acc[ni][0] = b0v; acc[ni][1] = b1v; acc[ni][2] = b0v; acc[ni][3] = b1v;
                }
            } else {
                const float* bm = bd + ((size_t)(e * 2 + 1) * N_ + n) * D_;
                const float blo = bm[v_m0 + g];
                const float bhi = bm[v_m0 + 8 + g];
                #pragma unroll
                for (int ni = 0; ni < 8; ++ni) {
                    acc[ni][0] = blo; acc[ni][1] = blo; acc[ni][2] = bhi; acc[ni][3] = bhi;
                }
            }
            #pragma unroll
            for (int s = 0; s < 4; ++s) {
                const u32* cur = WS + s * WBLK;
                #pragma unroll
                for (int kk = 0; kk < 2; ++kk) {
                    const int d2g = s * 16 + kk * 8;
                    const int w0  = (kk * 8 + tq) * 136;
                    const int w1  = (kk * 8 + tq + 4) * 136;
                    if (matId == 0) {
                        u32 a[4];
                        a[0] = XA[(k_m0 + g)     * 68 + d2g + tq];
                        a[1] = XA[(k_m0 + 8 + g) * 68 + d2g + tq];
                        a[2] = XA[(k_m0 + g)     * 68 + d2g + tq + 4];
                        a[3] = XA[(k_m0 + 8 + g) * 68 + d2g + tq + 4];
                        #pragma unroll
                        for (int ni = 0; ni < 8; ++ni) {
                            u32 bf[2];
                            bf[0] = cur[w0 + k_n0 + 8 * ni + g];
                            bf[1] = cur[w1 + k_n0 + 8 * ni + g];
                            mma_f16(acc[ni], a, bf);
                        }
                    } else {
                        const u32* cv = cur + WSLAB;
                        u32 a[4];
                        a[0] = cv[w0 + v_m0 + g];
                        a[1] = cv[w0 + v_m0 + 8 + g];
                        a[2] = cv[w1 + v_m0 + g];
                        a[3] = cv[w1 + v_m0 + 8 + g];
                        #pragma unroll
                        for (int ni = 0; ni < 8; ++ni) {
                            u32 bf[2];
                            bf[0] = XA[(8 * ni + g) * 68 + d2g + tq];
                            bf[1] = XA[(8 * ni + g) * 68 + d2g + tq + 4];
                            mma_f16(acc[ni], a, bf);
                        }
                    }
                }
            }
            if (matId == 0) {
                #pragma unroll
                for (int ni = 0; ni < 8; ++ni) {
                    KS[(k_m0 + g)     * 68 + k_n0 / 2 + 4 * ni + tq] = h2pack(acc[ni][0], acc[ni][1]);
                    KS[(k_m0 + 8 + g) * 68 + k_n0 / 2 + 4 * ni + tq] = h2pack(acc[ni][2], acc[ni][3]);
                }
            } else {
                #pragma unroll
                for (int ni = 0; ni < 8; ++ni) {
                    VT[(v_m0 + g)     * 36 + 4 * ni + tq] = h2pack(acc[ni][0], acc[ni][1]);
                    VT[(v_m0 + 8 + g) * 36 + 4 * ni + tq] = h2pack(acc[ni][2], acc[ni][3]);
                }
            }
            __syncthreads();
        }

        // prefetch Ws0+Ws1 (contiguous WDEXP u32) — hides behind att/softmax/PV
        {
            const u32* wssrc = WsT_g + (size_t)(e * 2) * 4 * WSLAB;
            #pragma unroll
            for (int j = tid; j < WDEXP / 4; j += 512)
                cp16(ws_s + (u32)(j * 16), wssrc + j * 4);
            CP_COMMIT();
        }

        // =================== att: S = Q K^T / 8 (per head) ===================
        {
            const int hb2 = h * 32;
            float sa[4][4];
            #pragma unroll
            for (int ni = 0; ni < 4; ++ni)
                #pragma unroll
                for (int c = 0; c < 4; ++c) sa[ni][c] = 0.f;
            #pragma unroll
            for (int ks = 0; ks < 4; ++ks) {
                const int d2g = hb2 + ks * 8;
                u32 a[4];
                a[0] = XA[(a_m0 + g)     * 68 + d2g + tq];
                a[1] = XA[(a_m0 + 8 + g) * 68 + d2g + tq];
                a[2] = XA[(a_m0 + g)     * 68 + d2g + tq + 4];
                a[3] = XA[(a_m0 + 8 + g) * 68 + d2g + tq + 4];
                #pragma unroll
                for (int ni = 0; ni < 4; ++ni) {
                    u32 bf[2];
                    bf[0] = KS[(a_n0 + 8 * ni + g) * 68 + d2g + tq];
                    bf[1] = KS[(a_n0 + 8 * ni + g) * 68 + d2g + tq + 4];
                    mma_f16(sa[ni], a, bf);
                }
            }
            float* Sh = S + h * 4352;
            #pragma unroll
            for (int ni = 0; ni < 4; ++ni) {
                const int cc = a_n0 + 8 * ni + 2 * tq;
                *(u64*)&Sh[(a_m0 + g)     * 68 + cc] = fpack(0.125f * sa[ni][0], 0.125f * sa[ni][1]);
                *(u64*)&Sh[(a_m0 + 8 + g) * 68 + cc] = fpack(0.125f * sa[ni][2], 0.125f * sa[ni][3]);
            }
            __syncthreads();
        }

        // =================== softmax -> P (half) ===================
        {
            __half* Pb = (__half*)PS;
            #pragma unroll
            for (int j = 0; j < 8; ++j) {
                const int r  = wid * 8 + j;
                const int hh = r >> 6;
                const int t  = r & 63;
                float* row = S + hh * 4352 + t * 68;
                const float a0 = row[lane];
                const float a1 = row[lane + 32];
                float m = fmaxf(a0, a1);
                #pragma unroll
                for (int o = 16; o > 0; o >>= 1) m = fmaxf(m, __shfl_xor_sync(0xffffffffu, m, o));
                const float e0 = __expf(a0 - m);
                const float e1 = __expf(a1 - m);
                float sum = e0 + e1;
                #pragma unroll
                for (int o = 16; o > 0; o >>= 1) sum += __shfl_xor_sync(0xffffffffu, sum, o);
                const float inv = 1.0f / sum;
                __half* Ph = Pb + hh * 4608 + t * 72;
                Ph[lane]      = __float2half_rn(e0 * inv);
                Ph[lane + 32] = __float2half_rn(e1 * inv);
            }
            __syncthreads();   // S dead after this point
        }

        // =================== O = P V (per head) ===================
        {
            const u32* Pu = PS + h * 2304;
            float oa[4][4];
            #pragma unroll
            for (int ni = 0; ni < 4; ++ni)
                #pragma unroll
                for (int c = 0; c < 4; ++c) oa[ni][c] = 0.f;
            #pragma unroll
            for (int ks = 0; ks < 4; ++ks) {
                const int kt2 = ks * 8;
                u32 a[4];
                a[0] = Pu[(a_m0 + g)     * 36 + kt2 + tq];
                a[1] = Pu[(a_m0 + 8 + g) * 36 + kt2 + tq];
                a[2] = Pu[(a_m0 + g)     * 36 + kt2 + tq + 4];
                a[3] = Pu[(a_m0 + 8 + g) * 36 + kt2 + tq + 4];
                #pragma unroll
                for (int ni = 0; ni < 4; ++ni) {
                    u32 bf[2];
                    bf[0] = VT[(h * 64 + a_n0 + 8 * ni + g) * 36 + kt2 + tq];
                    bf[1] = VT[(h * 64 + a_n0 + 8 * ni + g) * 36 + kt2 + tq + 4];
                    mma_f16(oa[ni], a, bf);
                }
            }
            #pragma unroll
            for (int ni = 0; ni < 4; ++ni) {
                const int c2 = h * 32 + a_n0 / 2 + 4 * ni + tq;
                OS[(a_m0 + g)     * 68 + c2] = h2pack(oa[ni][0], oa[ni][1]);
                OS[(a_m0 + 8 + g) * 68 + c2] = h2pack(oa[ni][2], oa[ni][3]);
            }
            CP_WAIT0();        // Ws staging complete
            __syncthreads();   // OS stores + Ws visible to all
        }

        // =================== GEMM2: O1 = relu(O @ Ws0 + bs0) ===================
        {
            const float* bsp = bs + (e * 2 + 0) * D_;
            float acc[4][4];
            #pragma unroll
            for (int ni = 0; ni < 4; ++ni) {
                const float b0v = bsp[g2_n0 + 8 * ni + 2 * tq];
                const float b1v = bsp[g2_n0 + 8 * ni + 2 * tq + 1];
                acc[ni][0] = b0v; acc[ni][1] = b1v; acc[ni][2] = b0v; acc[ni][3] = b1v;
            }
            #pragma unroll
            for (int s = 0; s < 4; ++s) {
                const u32* cur = WS + s * WSLAB;
                #pragma unroll
                for (int kk = 0; kk < 2; ++kk) {
                    const int d2g = s * 16 + kk * 8;
                    const int w0  = (kk * 8 + tq) * 136;
                    const int w1  = (kk * 8 + tq + 4) * 136;
                    u32 a[4];
                    a[0] = OS[(g2_m0 + g)     * 68 + d2g + tq];
                    a[1] = OS[(g2_m0 + 8 + g) * 68 + d2g + tq];
                    a[2] = OS[(g2_m0 + g)     * 68 + d2g + tq + 4];
                    a[3] = OS[(g2_m0 + 8 + g) * 68 + d2g + tq + 4];
                    #pragma unroll
                    for (int ni = 0; ni < 4; ++ni) {
                        u32 bf[2];
                        bf[0] = cur[w0 + g2_n0 + 8 * ni + g];
                        bf[1] = cur[w1 + g2_n0 + 8 * ni + g];
                        mma_f16(acc[ni], a, bf);
                    }
                }
            }
            #pragma unroll
            for (int ni = 0; ni < 4; ++ni) {
                const int c2 = g2_n0 / 2 + 4 * ni + tq;
                O1[(g2_m0 + g)     * 68 + c2] = h2pack(fmaxf(acc[ni][0], 0.f), fmaxf(acc[ni][1], 0.f));
                O1[(g2_m0 + 8 + g) * 68 + c2] = h2pack(fmaxf(acc[ni][2], 0.f), fmaxf(acc[ni][3], 0.f));
            }
            __syncthreads();
        }

        // =================== GEMM3: out_e = O1 @ Ws1 + bs1 ; accv += g*exp ===================
        {
            const float* bsp = bs + (e * 2 + 1) * D_;
            float acc[4][4];
            #pragma unroll
            for (int ni = 0; ni < 4; ++ni) {
                const float b0v = bsp[g2_n0 + 8 * ni + 2 * tq];
                const float b1v = bsp[g2_n0 + 8 * ni + 2 * tq + 1];
                acc[ni][0] = b0v; acc[ni][1] = b1v; acc[ni][2] = b0v; acc[ni][3] = b1v;
            }
            #pragma unroll
            for (int s = 0; s < 4; ++s) {
                const u32* cur = WS + 4 * WSLAB + s * WSLAB;
                #pragma unroll
                for (int kk = 0; kk < 2; ++kk) {
                    const int d2g = s * 16 + kk * 8;
                    const int w0  = (kk * 8 + tq) * 136;
                    const int w1  = (kk * 8 + tq + 4) * 136;
                    u32 a[4];
                    a[0] = O1[(g2_m0 + g)     * 68 + d2g + tq];
                    a[1] = O1[(g2_m0 + 8 + g) * 68 + d2g + tq];
                    a[2] = O1[(g2_m0 + g)     * 68 + d2g + tq + 4];
                    a[3] = O1[(g2_m0 + 8 + g) * 68 + d2g + tq + 4];
                    #pragma unroll
                    for (int ni = 0; ni < 4; ++ni) {
                        u32 bf[2];
                        bf[0] = cur[w0 + g2_n0 + 8 * ni + g];
                        bf[1] = cur[w1 + g2_n0 + 8 * ni + g];
                        mma_f16(acc[ni], a, bf);
                    }
                }
            }
            #pragma unroll
            for (int ni = 0; ni < 4; ++ni)
                #pragma unroll
                for (int c = 0; c < 4; ++c)
                    accv[ni][c] += gg * __expf(acc[ni][c]);
            __syncthreads();   // WS reads done before next expert's staging
        }

        // issue next expert's Wd staging (waited at next loop top)
        if (slot + 1 < K_) {
            const int e1 = d_eidx[b][slot + 1];
            const u32* wdsrc = WdT_g + (size_t)(e1 * 32 + n) * WDEXP;
            #pragma unroll
            for (int j = tid; j < WDEXP / 4; j += 512)
                cp16(ws_s + (u32)(j * 16), wdsrc + j * 4);
            CP_COMMIT();
        }
    }

    // ---- combine epilogue ----
    const float EPSF = 2.2204460492503131e-16f;
    #pragma unroll
    for (int ni = 0; ni < 4; ++ni) {
        const int cc  = g2_n0 + 8 * ni + 2 * tq;
        const int t0r = g2_m0 + g;
        const int t1r = g2_m0 + 8 + g;
        float v0 = accv[ni][0]; if (v0 == 0.f) v0 = EPSF;
        float v1 = accv[ni][1]; if (v1 == 0.f) v1 = EPSF;
        float v2 = accv[ni][2]; if (v2 == 0.f) v2 = EPSF;
        float v3 = accv[ni][3]; if (v3 == 0.f) v3 = EPSF;
        *(u64*)&out[(((size_t)b * T_ + t0r) * N_ + n) * D_ + cc] = fpack(__logf(v0), __logf(v1));
        *(u64*)&out[(((size_t)b * T_ + t1r) * N_ + n) * D_ + cc] = fpack(__logf(v2), __logf(v3));
    }
}

// ---------------------------------------------------------------------------
// launcher
// ---------------------------------------------------------------------------
extern "C" void kernel_launch(void* const* d_in, const int* in_sizes, int n_in,
                              void* d_out, int out_size) {
    const float* x  = (const float*)d_in[0];
    const float* Wg = (const float*)d_in[1];
    const float* Wd = (const float*)d_in[2];
    const float* bd = (const float*)d_in[3];
    const float* Ws = (const float*)d_in[4];
    const float* bs = (const float*)d_in[5];
    float* out = (float*)d_out;

    const int smem_bytes = SMEM_U * 4; // 176128 B
    cudaFuncSetAttribute(moe_kernel, cudaFuncAttributeMaxDynamicSharedMemorySize, smem_bytes);

    prep_gate_kernel<<<3136, 256>>>(Wd, Ws, x);
    gate_kernel<<<B_, 128>>>(Wg);
    dim3 grid(N_, B_);
    moe_kernel<<<grid, 512, smem_bytes>>>(x, bd, bs, out);
}

// round 16
// speedup vs baseline: 1.0644x; 1.0112x over previous
#include <cuda_runtime.h>
#include <cuda_fp16.h>
#include <math.h>

#define B_ 32
#define T_ 64
#define N_ 32
#define D_ 128
#define E_ 8
#define K_ 2

typedef unsigned long long u64;
typedef unsigned int u32;

// SMEM u32-unit offsets
#define OFF_XA  0        // x     [64][68]  half2 (d-pairs)
#define OFF_KS  4352     // K     [64][68]  half2 (dc-pairs)
#define OFF_VT  8704     // V^T   [128][36] half2 (t-pairs)
#define OFF_PS  13312    // P     [2][64][36] half2 (kt-pairs)
#define OFF_OS  17920    // O     [64][68]  half2   (S overlays OS+O1)
#define OFF_O1  22272    // O1    [64][68]  half2
#define OFF_WS  26624    // weight buffer: 17408 u32 (68KB)
#define SMEM_U  44032    // *4 = 176128 bytes

// weight slab layout: [d2][c] stride 136 (16 rows x 128 cols + 8 pad)
#define WSLAB   2176     // u32 per matrix slab
#define WBLK    4352     // u32 per (mat0+mat1) slab pair
#define WDEXP   17408    // u32 per (e,n) full Wd  (= Ws0+Ws1 total too)

#define NTILES  (B_ * N_)   // 1024
#define GRIDP   148

__device__ int   d_eidx[B_][K_];
__device__ float d_gateg[B_][K_];
__device__ float d_part[B_][64][D_];

// Pre-converted fp16 weights: [d2][c]-major, stride 136
__device__ u32 WdT_g[8 * 32 * WDEXP];      // ~17 MB
__device__ u32 WsT_g[16 * 4 * WSLAB];      // 545 KB

__device__ __forceinline__ u64 fpack(float lo, float hi) {
    u64 d; asm("mov.b64 %0, {%1, %2};" : "=l"(d) : "f"(lo), "f"(hi)); return d;
}
__device__ __forceinline__ u32 h2pack(float lo, float hi) {
    __half2 h = __floats2half2_rn(lo, hi);
    return *(u32*)&h;
}
__device__ __forceinline__ void mma_f16(float* c, const u32* a, const u32* b) {
    asm volatile(
        "mma.sync.aligned.m16n8k16.row.col.f32.f16.f16.f32 "
        "{%0,%1,%2,%3}, {%4,%5,%6,%7}, {%8,%9}, {%0,%1,%2,%3};\n"
        : "+f"(c[0]), "+f"(c[1]), "+f"(c[2]), "+f"(c[3])
        : "r"(a[0]), "r"(a[1]), "r"(a[2]), "r"(a[3]), "r"(b[0]), "r"(b[1]));
}
__device__ __forceinline__ void cp16(u32 smem_addr, const void* gptr) {
    asm volatile("cp.async.cg.shared.global [%0], [%1], 16;" :: "r"(smem_addr), "l"(gptr));
}
#define CP_COMMIT() asm volatile("cp.async.commit_group;")
#define CP_WAIT0()  asm volatile("cp.async.wait_group 0;")

// ---------------------------------------------------------------------------
// Fused prep (vectorized, transpose-free) + gate_partial. 3136 CTAs.
// ---------------------------------------------------------------------------
__global__ void prep_gate_kernel(const float* __restrict__ Wd,
                                 const float* __restrict__ Ws,
                                 const float* __restrict__ x) {
    const int bid = blockIdx.x;
    const int tid = threadIdx.x;   // 256
    if (bid < 2112) {
        const float* src;
        u32* dst;
        if (bid < 2048) {
            const int s = bid & 3, mat = (bid >> 2) & 1, n = (bid >> 3) & 31, e = bid >> 8;
            src = Wd + ((size_t)(e * 2 + mat) * 32 + n) * (128 * 128) + s * 32 * 128;
            dst = WdT_g + ((size_t)(e * 32 + n)) * WDEXP + s * WBLK + mat * WSLAB;
        } else {
            const int r = bid - 2048;
            const int s = r & 3, em = r >> 2;
            src = Ws + (size_t)em * (128 * 128) + s * 32 * 128;
            dst = WsT_g + ((size_t)em * 4 + s) * WSLAB;
        }
        // 512 uint4 outputs; 2 per thread; float4 reads both rows (high MLP)
        #pragma unroll
        for (int q = tid; q < 512; q += 256) {
            const int d2 = q >> 5;
            const int c4 = (q & 31) * 4;
            const float4 r0 = *(const float4*)&src[(2 * d2) * 128 + c4];
            const float4 r1 = *(const float4*)&src[(2 * d2 + 1) * 128 + c4];
            uint4 o;
            o.x = h2pack(r0.x, r1.x); o.y = h2pack(r0.y, r1.y);
            o.z = h2pack(r0.z, r1.z); o.w = h2pack(r0.w, r1.w);
            *(uint4*)&dst[d2 * 136 + c4] = o;
        }
    } else {
        const int r    = bid - 2112;        // 0..1023
        const int b    = r >> 5, ch = r & 31;
        const int sub  = tid >> 7;          // 0/1
        const int lane = tid & 127;
        const float* base = x + ((size_t)b * T_ * N_ + ch * 64 + sub * 32) * D_;
        float s = 0.f;
        #pragma unroll 8
        for (int rr = 0; rr < 32; ++rr) s += base[rr * D_ + lane];
        d_part[b][ch * 2 + sub][lane] = s;
    }
}

// ---------------------------------------------------------------------------
// Gating stage 2
// ---------------------------------------------------------------------------
__global__ void gate_kernel(const float* __restrict__ Wg) {
    const int b   = blockIdx.x;
    const int tid = threadIdx.x;   // 128
    __shared__ float smean[D_];
    __shared__ float slog[E_];

    float s = 0.f;
    #pragma unroll
    for (int c = 0; c < 64; ++c) s += d_part[b][c][tid];
    smean[tid] = s * (1.0f / (float)(T_ * N_));
    __syncthreads();

    if (tid < E_) {
        float l = 0.f;
        for (int d = 0; d < D_; ++d) l += smean[d] * Wg[d * E_ + tid];
        slog[tid] = l;
    }
    __syncthreads();

    if (tid == 0) {
        int i0 = 0; float v0 = slog[0];
        for (int e = 1; e < E_; ++e) if (slog[e] > v0) { v0 = slog[e]; i0 = e; }
        int i1 = -1; float v1 = -3.0e38f;
        for (int e = 0; e < E_; ++e) if (e != i0 && slog[e] > v1) { v1 = slog[e]; i1 = e; }
        const float e1  = expf(v1 - v0);
        const float inv = 1.0f / (1.0f + e1);
        d_eidx[b][0]  = i0; d_eidx[b][1]  = i1;
        d_gateg[b][0] = inv; d_gateg[b][1] = e1 * inv;
    }
}

// ---------------------------------------------------------------------------
// x tile loader: [T][D] -> XA half2 (stride 68)
// ---------------------------------------------------------------------------
__device__ __forceinline__ void load_x_tile(u32* XA, const float* __restrict__ x,
                                            int b, int n, int tid) {
    const float4* xg = (const float4*)(x + ((size_t)b * T_ * N_ + n) * D_);
    #pragma unroll
    for (int i = tid; i < T_ * D_ / 4; i += 512) {
        const int t  = i >> 5;
        const int c2 = (i & 31) * 2;
        float4 v = xg[(size_t)t * (N_ * D_ / 4) + (i & 31)];
        XA[t * 68 + c2]     = h2pack(v.x, v.y);
        XA[t * 68 + c2 + 1] = h2pack(v.z, v.w);
    }
}

// ---------------------------------------------------------------------------
// Kernel 2: persistent (148 CTAs x ~7 tiles). fp16 mma, [d2][c] weight slabs.
// Next tile's x prefetched after att(slot1); next Wd staged at loop end.
// ---------------------------------------------------------------------------
__global__ __launch_bounds__(512, 1)
void moe_kernel(const float* __restrict__ x,
                const float* __restrict__ bd,
                const float* __restrict__ bs,
                float* __restrict__ out) {
    extern __shared__ u32 smu[];
    u32*   XA = smu + OFF_XA;
    u32*   KS = smu + OFF_KS;
    u32*   VT = smu + OFF_VT;
    u32*   PS = smu + OFF_PS;
    u32*   OS = smu + OFF_OS;
    u32*   O1 = smu + OFF_O1;
    u32*   WS = smu + OFF_WS;
    float* S  = (float*)(smu + OFF_OS);

    const u32 ws_s = (u32)__cvta_generic_to_shared(WS);

    const int tid  = threadIdx.x;
    const int lane = tid & 31;
    const int wid  = tid >> 5;
    const int g    = lane >> 2;
    const int tq   = lane & 3;

    // mappings
    const int matId = wid >> 3;
    const int k_m0  = (wid & 3) * 16;
    const int k_n0  = ((wid >> 2) & 1) * 64;
    const int v_m0  = (wid & 7) * 16;
    const int h     = wid >> 3;
    const int a_m0  = (wid & 3) * 16;
    const int a_n0  = ((wid >> 2) & 1) * 32;
    const int g2_m0 = (wid & 3) * 16;
    const int g2_n0 = (wid >> 2) * 32;

    int tile = blockIdx.x;
    if (tile >= NTILES) return;
    int n = tile & 31;
    int b = tile >> 5;

    // prologue: stage Wd(e0) of first tile; load first x tile
    {
        const int e0 = d_eidx[b][0];
        const u32* wdsrc = WdT_g + (size_t)(e0 * 32 + n) * WDEXP;
        #pragma unroll
        for (int j = tid; j < WDEXP / 4; j += 512)
            cp16(ws_s + (u32)(j * 16), wdsrc + j * 4);
        CP_COMMIT();
    }
    load_x_tile(XA, x, b, n, tid);

    while (true) {
        const int  ntile   = tile + GRIDP;
        const bool hasNext = (ntile < NTILES);
        const int  nn = ntile & 31;
        const int  nb = ntile >> 5;

        float accv[4][4];
        #pragma unroll
        for (int ni = 0; ni < 4; ++ni)
            #pragma unroll
            for (int c = 0; c < 4; ++c) accv[ni][c] = 0.f;

        for (int slot = 0; slot < K_; ++slot) {
            const int   e  = d_eidx[b][slot];
            const float gg = d_gateg[b][slot];

            // wait pending Wd staging (+ XA stores)
            CP_WAIT0();
            __syncthreads();

            // =================== GEMM1: K = x@W0+b0 ; V^T = W1^T@x^T + b1 ===================
            {
                float acc[8][4];
                if (matId == 0) {
                    const float* bm = bd + ((size_t)(e * 2 + 0) * N_ + n) * D_;
                    #pragma unroll
                    for (int ni = 0; ni < 8; ++ni) {
                        const float b0v = bm[k_n0 + 8 * ni + 2 * tq];
                        const float b1v = bm[k_n0 + 8 * ni + 2 * tq + 1];
                        acc[ni][0] = b0v; acc[ni][1] = b1v; acc[ni][2] = b0v; acc[ni][3] = b1v;
                    }
                } else {
                    const float* bm = bd + ((size_t)(e * 2 + 1) * N_ + n) * D_;
                    const float blo = bm[v_m0 + g];
                    const float bhi = bm[v_m0 + 8 + g];
                    #pragma unroll
                    for (int ni = 0; ni < 8; ++ni) {
                        acc[ni][0] = blo; acc[ni][1] = blo; acc[ni][2] = bhi; acc[ni][3] = bhi;
                    }
                }
                #pragma unroll
                for (int s = 0; s < 4; ++s) {
                    const u32* cur = WS + s * WBLK;
                    #pragma unroll
                    for (int kk = 0; kk < 2; ++kk) {
                        const int d2g = s * 16 + kk * 8;
                        const int w0  = (kk * 8 + tq) * 136;
                        const int w1  = (kk * 8 + tq + 4) * 136;
                        if (matId == 0) {
                            u32 a[4];
                            a[0] = XA[(k_m0 + g)     * 68 + d2g + tq];
                            a[1] = XA[(k_m0 + 8 + g) * 68 + d2g + tq];
                            a[2] = XA[(k_m0 + g)     * 68 + d2g + tq + 4];
                            a[3] = XA[(k_m0 + 8 + g) * 68 + d2g + tq + 4];
                            #pragma unroll
                            for (int ni = 0; ni < 8; ++ni) {
                                u32 bf[2];
                                bf[0] = cur[w0 + k_n0 + 8 * ni + g];
                                bf[1] = cur[w1 + k_n0 + 8 * ni + g];
                                mma_f16(acc[ni], a, bf);
                            }
                        } else {
                            const u32* cv = cur + WSLAB;
                            u32 a[4];
                            a[0] = cv[w0 + v_m0 + g];
                            a[1] = cv[w0 + v_m0 + 8 + g];
                            a[2] = cv[w1 + v_m0 + g];
                            a[3] = cv[w1 + v_m0 + 8 + g];
                            #pragma unroll
                            for (int ni = 0; ni < 8; ++ni) {
                                u32 bf[2];
                                bf[0] = XA[(8 * ni + g) * 68 + d2g + tq];
                                bf[1] = XA[(8 * ni + g) * 68 + d2g + tq + 4];
                                mma_f16(acc[ni], a, bf);
                            }
                        }
                    }
                }
                if (matId == 0) {
                    #pragma unroll
                    for (int ni = 0; ni < 8; ++ni) {
                        KS[(k_m0 + g)     * 68 + k_n0 / 2 + 4 * ni + tq] = h2pack(acc[ni][0], acc[ni][1]);
                        KS[(k_m0 + 8 + g) * 68 + k_n0 / 2 + 4 * ni + tq] = h2pack(acc[ni][2], acc[ni][3]);
                    }
                } else {
                    #pragma unroll
                    for (int ni = 0; ni < 8; ++ni) {
                        VT[(v_m0 + g)     * 36 + 4 * ni + tq] = h2pack(acc[ni][0], acc[ni][1]);
                        VT[(v_m0 + 8 + g) * 36 + 4 * ni + tq] = h2pack(acc[ni][2], acc[ni][3]);
                    }
                }
                __syncthreads();
            }

            // prefetch Ws0+Ws1 — hides behind att/softmax/PV
            {
                const u32* wssrc = WsT_g + (size_t)(e * 2) * 4 * WSLAB;
                #pragma unroll
                for (int j = tid; j < WDEXP / 4; j += 512)
                    cp16(ws_s + (u32)(j * 16), wssrc + j * 4);
                CP_COMMIT();
            }

            // =================== att: S = Q K^T / 8 (per head) ===================
            {
                const int hb2 = h * 32;
                float sa[4][4];
                #pragma unroll
                for (int ni = 0; ni < 4; ++ni)
                    #pragma unroll
                    for (int c = 0; c < 4; ++c) sa[ni][c] = 0.f;
                #pragma unroll
                for (int ks = 0; ks < 4; ++ks) {
                    const int d2g = hb2 + ks * 8;
                    u32 a[4];
                    a[0] = XA[(a_m0 + g)     * 68 + d2g + tq];
                    a[1] = XA[(a_m0 + 8 + g) * 68 + d2g + tq];
                    a[2] = XA[(a_m0 + g)     * 68 + d2g + tq + 4];
                    a[3] = XA[(a_m0 + 8 + g) * 68 + d2g + tq + 4];
                    #pragma unroll
                    for (int ni = 0; ni < 4; ++ni) {
                        u32 bf[2];
                        bf[0] = KS[(a_n0 + 8 * ni + g) * 68 + d2g + tq];
                        bf[1] = KS[(a_n0 + 8 * ni + g) * 68 + d2g + tq + 4];
                        mma_f16(sa[ni], a, bf);
                    }
                }
                float* Sh = S + h * 4352;
                #pragma unroll
                for (int ni = 0; ni < 4; ++ni) {
                    const int cc = a_n0 + 8 * ni + 2 * tq;
                    *(u64*)&Sh[(a_m0 + g)     * 68 + cc] = fpack(0.125f * sa[ni][0], 0.125f * sa[ni][1]);
                    *(u64*)&Sh[(a_m0 + 8 + g) * 68 + cc] = fpack(0.125f * sa[ni][2], 0.125f * sa[ni][3]);
                }
                __syncthreads();
            }

            // after att of slot 1, XA is dead: prefetch next tile's x
            if (slot == 1 && hasNext)
                load_x_tile(XA, x, nb, nn, tid);

            // =================== softmax -> P (half) ===================
            {
                __half* Pb = (__half*)PS;
                #pragma unroll
                for (int j = 0; j < 8; ++j) {
                    const int r  = wid * 8 + j;
                    const int hh = r >> 6;
                    const int t  = r & 63;
                    float* row = S + hh * 4352 + t * 68;
                    const float a0 = row[lane];
                    const float a1 = row[lane + 32];
                    float m = fmaxf(a0, a1);
                    #pragma unroll
                    for (int o = 16; o > 0; o >>= 1) m = fmaxf(m, __shfl_xor_sync(0xffffffffu, m, o));
                    const float e0 = __expf(a0 - m);
                    const float e1 = __expf(a1 - m);
                    float sum = e0 + e1;
                    #pragma unroll
                    for (int o = 16; o > 0; o >>= 1) sum += __shfl_xor_sync(0xffffffffu, sum, o);
                    const float inv = 1.0f / sum;
                    __half* Ph = Pb + hh * 4608 + t * 72;
                    Ph[lane]      = __float2half_rn(e0 * inv);
                    Ph[lane + 32] = __float2half_rn(e1 * inv);
                }
                __syncthreads();
            }

            // =================== O = P V (per head) ===================
            {
                const u32* Pu = PS + h * 2304;
                float oa[4][4];
                #pragma unroll
                for (int ni = 0; ni < 4; ++ni)
                    #pragma unroll
                    for (int c = 0; c < 4; ++c) oa[ni][c] = 0.f;
                #pragma unroll
                for (int ks = 0; ks < 4; ++ks) {
                    const int kt2 = ks * 8;
                    u32 a[4];
                    a[0] = Pu[(a_m0 + g)     * 36 + kt2 + tq];
                    a[1] = Pu[(a_m0 + 8 + g) * 36 + kt2 + tq];
                    a[2] = Pu[(a_m0 + g)     * 36 + kt2 + tq + 4];
                    a[3] = Pu[(a_m0 + 8 + g) * 36 + kt2 + tq + 4];
                    #pragma unroll
                    for (int ni = 0; ni < 4; ++ni) {
                        u32 bf[2];
                        bf[0] = VT[(h * 64 + a_n0 + 8 * ni + g) * 36 + kt2 + tq];
                        bf[1] = VT[(h * 64 + a_n0 + 8 * ni + g) * 36 + kt2 + tq + 4];
                        mma_f16(oa[ni], a, bf);
                    }
                }
                #pragma unroll
                for (int ni = 0; ni < 4; ++ni) {
                    const int c2 = h * 32 + a_n0 / 2 + 4 * ni + tq;
                    OS[(a_m0 + g)     * 68 + c2] = h2pack(oa[ni][0], oa[ni][1]);
                    OS[(a_m0 + 8 + g) * 68 + c2] = h2pack(oa[ni][2], oa[ni][3]);
                }
                CP_WAIT0();        // Ws staging complete
                __syncthreads();   // OS stores + Ws visible to all
            }

            // =================== GEMM2: O1 = relu(O @ Ws0 + bs0) ===================
            {
                const float* bsp = bs + (e * 2 + 0) * D_;
                float acc[4][4];
                #pragma unroll
                for (int ni = 0; ni < 4; ++ni) {
                    const float b0v = bsp[g2_n0 + 8 * ni + 2 * tq];
                    const float b1v = bsp[g2_n0 + 8 * ni + 2 * tq + 1];
                    acc[ni][0] = b0v; acc[ni][1] = b1v; acc[ni][2] = b0v; acc[ni][3] = b1v;
                }
                #pragma unroll
                for (int s = 0; s < 4; ++s) {
                    const u32* cur = WS + s * WSLAB;
                    #pragma unroll
                    for (int kk = 0; kk < 2; ++kk) {
                        const int d2g = s * 16 + kk * 8;
                        const int w0  = (kk * 8 + tq) * 136;
                        const int w1  = (kk * 8 + tq + 4) * 136;
                        u32 a[4];
                        a[0] = OS[(g2_m0 + g)     * 68 + d2g + tq];
                        a[1] = OS[(g2_m0 + 8 + g) * 68 + d2g + tq];
                        a[2] = OS[(g2_m0 + g)     * 68 + d2g + tq + 4];
                        a[3] = OS[(g2_m0 + 8 + g) * 68 + d2g + tq + 4];
                        #pragma unroll
                        for (int ni = 0; ni < 4; ++ni) {
                            u32 bf[2];
                            bf[0] = cur[w0 + g2_n0 + 8 * ni + g];
                            bf[1] = cur[w1 + g2_n0 + 8 * ni + g];
                            mma_f16(acc[ni], a, bf);
                        }
                    }
                }
                #pragma unroll
                for (int ni = 0; ni < 4; ++ni) {
                    const int c2 = g2_n0 / 2 + 4 * ni + tq;
                    O1[(g2_m0 + g)     * 68 + c2] = h2pack(fmaxf(acc[ni][0], 0.f), fmaxf(acc[ni][1], 0.f));
                    O1[(g2_m0 + 8 + g) * 68 + c2] = h2pack(fmaxf(acc[ni][2], 0.f), fmaxf(acc[ni][3], 0.f));
                }
                __syncthreads();
            }

            // =================== GEMM3: out_e = O1 @ Ws1 + bs1 ; accv += g*exp ===================
            {
                const float* bsp = bs + (e * 2 + 1) * D_;
                float acc[4][4];
                #pragma unroll
                for (int ni = 0; ni < 4; ++ni) {
                    const float b0v = bsp[g2_n0 + 8 * ni + 2 * tq];
                    const float b1v = bsp[g2_n0 + 8 * ni + 2 * tq + 1];
                    acc[ni][0] = b0v; acc[ni][1] = b1v; acc[ni][2] = b0v; acc[ni][3] = b1v;
                }
                #pragma unroll
                for (int s = 0; s < 4; ++s) {
                    const u32* cur = WS + 4 * WSLAB + s * WSLAB;
                    #pragma unroll
                    for (int kk = 0; kk < 2; ++kk) {
                        const int d2g = s * 16 + kk * 8;
                        const int w0  = (kk * 8 + tq) * 136;
                        const int w1  = (kk * 8 + tq + 4) * 136;
                        u32 a[4];
                        a[0] = O1[(g2_m0 + g)     * 68 + d2g + tq];
                        a[1] = O1[(g2_m0 + 8 + g) * 68 + d2g + tq];
                        a[2] = O1[(g2_m0 + g)     * 68 + d2g + tq + 4];
                        a[3] = O1[(g2_m0 + 8 + g) * 68 + d2g + tq + 4];
                        #pragma unroll
                        for (int ni = 0; ni < 4; ++ni) {
                            u32 bf[2];
                            bf[0] = cur[w0 + g2_n0 + 8 * ni + g];
                            bf[1] = cur[w1 + g2_n0 + 8 * ni + g];
                            mma_f16(acc[ni], a, bf);
                        }
                    }
                }
                #pragma unroll
                for (int ni = 0; ni < 4; ++ni)
                    #pragma unroll
                    for (int c = 0; c < 4; ++c)
                        accv[ni][c] += gg * __expf(acc[ni][c]);
                __syncthreads();   // WS reads done before next staging
            }

            // stage next weights: e1 (slot 0) or next tile's e0 (slot 1)
            if (slot == 0) {
                const int e1 = d_eidx[b][1];
                const u32* wdsrc = WdT_g + (size_t)(e1 * 32 + n) * WDEXP;
                #pragma unroll
                for (int j = tid; j < WDEXP / 4; j += 512)
                    cp16(ws_s + (u32)(j * 16), wdsrc + j * 4);
                CP_COMMIT();
            } else if (hasNext) {
                const int e0n = d_eidx[nb][0];
                const u32* wdsrc = WdT_g + (size_t)(e0n * 32 + nn) * WDEXP;
                #pragma unroll
                for (int j = tid; j < WDEXP / 4; j += 512)
                    cp16(ws_s + (u32)(j * 16), wdsrc + j * 4);
                CP_COMMIT();
            }
        }

        // ---- combine epilogue for this tile ----
        const float EPSF = 2.2204460492503131e-16f;
        #pragma unroll
        for (int ni = 0; ni < 4; ++ni) {
            const int cc  = g2_n0 + 8 * ni + 2 * tq;
            const int t0r = g2_m0 + g;
            const int t1r = g2_m0 + 8 + g;
            float v0 = accv[ni][0]; if (v0 == 0.f) v0 = EPSF;
            float v1 = accv[ni][1]; if (v1 == 0.f) v1 = EPSF;
            float v2 = accv[ni][2]; if (v2 == 0.f) v2 = EPSF;
            float v3 = accv[ni][3]; if (v3 == 0.f) v3 = EPSF;
            *(u64*)&out[(((size_t)b * T_ + t0r) * N_ + n) * D_ + cc] = fpack(__logf(v0), __logf(v1));
            *(u64*)&out[(((size_t)b * T_ + t1r) * N_ + n) * D_ + cc] = fpack(__logf(v2), __logf(v3));
        }

        if (!hasNext) break;
        tile = ntile; n = nn; b = nb;
    }
}

// ---------------------------------------------------------------------------
// launcher
// ---------------------------------------------------------------------------
extern "C" void kernel_launch(void* const* d_in, const int* in_sizes, int n_in,
                              void* d_out, int out_size) {
    const float* x  = (const float*)d_in[0];
    const float* Wg = (const float*)d_in[1];
    const float* Wd = (const float*)d_in[2];
    const float* bd = (const float*)d_in[3];
    const float* Ws = (const float*)d_in[4];
    const float* bs = (const float*)d_in[5];
    float* out = (float*)d_out;

    const int smem_bytes = SMEM_U * 4; // 176128 B
    cudaFuncSetAttribute(moe_kernel, cudaFuncAttributeMaxDynamicSharedMemorySize, smem_bytes);

    prep_gate_kernel<<<3136, 256>>>(Wd, Ws, x);
    gate_kernel<<<B_, 128>>>(Wg);
    moe_kernel<<<GRIDP, 512, smem_bytes>>>(x, bd, bs, out);
}

// round 17
// speedup vs baseline: 1.0708x; 1.0061x over previous
#include <cuda_runtime.h>
#include <cuda_fp16.h>
#include <math.h>

#define B_ 32
#define T_ 64
#define N_ 32
#define D_ 128
#define E_ 8
#define K_ 2

typedef unsigned long long u64;
typedef unsigned int u32;

// SMEM u32-unit offsets
#define OFF_XA  0        // x     [64][68]  half2 (d-pairs)
#define OFF_KS  4352     // K     [64][68]  half2 (dc-pairs)
#define OFF_VT  8704     // V^T   [128][36] half2 (t-pairs)
#define OFF_PS  13312    // P     [2][64][36] half2 (kt-pairs)
#define OFF_OS  17920    // O     [64][68]  half2   (S overlays OS+O1)
#define OFF_O1  22272    // O1    [64][68]  half2
#define OFF_WS  26624    // weight buffer: 17408 u32 (68KB)
#define SMEM_U  44032    // *4 = 176128 bytes

// weight slab layout: [d2][c] stride 136 (16 rows x 128 cols + 8 pad)
#define WSLAB   2176
#define WBLK    4352
#define WDEXP   17408

#define NTILES  (B_ * N_)   // 1024
#define GRIDP   148

__device__ int   d_eidx[B_][K_];
__device__ float d_gateg[B_][K_];
__device__ float d_part[B_][128][D_];

__device__ u32 WdT_g[8 * 32 * WDEXP];      // ~17 MB
__device__ u32 WsT_g[16 * 4 * WSLAB];      // 545 KB

__device__ __forceinline__ u64 fpack(float lo, float hi) {
    u64 d; asm("mov.b64 %0, {%1, %2};" : "=l"(d) : "f"(lo), "f"(hi)); return d;
}
__device__ __forceinline__ u32 h2pack(float lo, float hi) {
    __half2 h = __floats2half2_rn(lo, hi);
    return *(u32*)&h;
}
__device__ __forceinline__ void mma_f16(float* c, const u32* a, const u32* b) {
    asm volatile(
        "mma.sync.aligned.m16n8k16.row.col.f32.f16.f16.f32 "
        "{%0,%1,%2,%3}, {%4,%5,%6,%7}, {%8,%9}, {%0,%1,%2,%3};\n"
        : "+f"(c[0]), "+f"(c[1]), "+f"(c[2]), "+f"(c[3])
        : "r"(a[0]), "r"(a[1]), "r"(a[2]), "r"(a[3]), "r"(b[0]), "r"(b[1]));
}
__device__ __forceinline__ void cp16(u32 smem_addr, const void* gptr) {
    asm volatile("cp.async.cg.shared.global [%0], [%1], 16;" :: "r"(smem_addr), "l"(gptr));
}
#define CP_COMMIT() asm volatile("cp.async.commit_group;")
#define CP_WAIT0()  asm volatile("cp.async.wait_group 0;")

// ---------------------------------------------------------------------------
// Fused prep (vectorized, 1 uint4/thread) + gate_partial (4-way split)
// ---------------------------------------------------------------------------
__global__ void prep_gate_kernel(const float* __restrict__ Wd,
                                 const float* __restrict__ Ws,
                                 const float* __restrict__ x) {
    const int bid = blockIdx.x;
    const int tid = threadIdx.x;   // 512
    if (bid < 2112) {
        const float* src;
        u32* dst;
        if (bid < 2048) {
            const int s = bid & 3, mat = (bid >> 2) & 1, n = (bid >> 3) & 31, e = bid >> 8;
            src = Wd + ((size_t)(e * 2 + mat) * 32 + n) * (128 * 128) + s * 32 * 128;
            dst = WdT_g + ((size_t)(e * 32 + n)) * WDEXP + s * WBLK + mat * WSLAB;
        } else {
            const int r = bid - 2048;
            const int s = r & 3, em = r >> 2;
            src = Ws + (size_t)em * (128 * 128) + s * 32 * 128;
            dst = WsT_g + ((size_t)em * 4 + s) * WSLAB;
        }
        const int d2 = tid >> 5;
        const int c4 = (tid & 31) * 4;
        const float4 r0 = *(const float4*)&src[(2 * d2) * 128 + c4];
        const float4 r1 = *(const float4*)&src[(2 * d2 + 1) * 128 + c4];
        uint4 o;
        o.x = h2pack(r0.x, r1.x); o.y = h2pack(r0.y, r1.y);
        o.z = h2pack(r0.z, r1.z); o.w = h2pack(r0.w, r1.w);
        *(uint4*)&dst[d2 * 136 + c4] = o;
    } else {
        const int r    = bid - 2112;        // 0..1023
        const int b    = r >> 5, ch = r & 31;
        const int sub  = tid >> 7;          // 0..3
        const int lane = tid & 127;
        const float* base = x + ((size_t)b * T_ * N_ + ch * 64 + sub * 16) * D_;
        float s = 0.f;
        #pragma unroll 8
        for (int rr = 0; rr < 16; ++rr) s += base[rr * D_ + lane];
        d_part[b][ch * 4 + sub][lane] = s;
    }
}

// ---------------------------------------------------------------------------
// Gating stage 2
// ---------------------------------------------------------------------------
__global__ void gate_kernel(const float* __restrict__ Wg) {
    const int b   = blockIdx.x;
    const int tid = threadIdx.x;   // 128
    __shared__ float smean[D_];
    __shared__ float slog[E_];

    float s = 0.f;
    #pragma unroll
    for (int c = 0; c < 128; ++c) s += d_part[b][c][tid];
    smean[tid] = s * (1.0f / (float)(T_ * N_));
    __syncthreads();

    if (tid < E_) {
        float l = 0.f;
        for (int d = 0; d < D_; ++d) l += smean[d] * Wg[d * E_ + tid];
        slog[tid] = l;
    }
    __syncthreads();

    if (tid == 0) {
        int i0 = 0; float v0 = slog[0];
        for (int e = 1; e < E_; ++e) if (slog[e] > v0) { v0 = slog[e]; i0 = e; }
        int i1 = -1; float v1 = -3.0e38f;
        for (int e = 0; e < E_; ++e) if (e != i0 && slog[e] > v1) { v1 = slog[e]; i1 = e; }
        const float e1  = expf(v1 - v0);
        const float inv = 1.0f / (1.0f + e1);
        d_eidx[b][0]  = i0; d_eidx[b][1]  = i1;
        d_gateg[b][0] = inv; d_gateg[b][1] = e1 * inv;
    }
}

// ---------------------------------------------------------------------------
// x tile loader
// ---------------------------------------------------------------------------
__device__ __forceinline__ void load_x_tile(u32* XA, const float* __restrict__ x,
                                            int b, int n, int tid) {
    const float4* xg = (const float4*)(x + ((size_t)b * T_ * N_ + n) * D_);
    #pragma unroll
    for (int i = tid; i < T_ * D_ / 4; i += 512) {
        const int t  = i >> 5;
        const int c2 = (i & 31) * 2;
        float4 v = xg[(size_t)t * (N_ * D_ / 4) + (i & 31)];
        XA[t * 68 + c2]     = h2pack(v.x, v.y);
        XA[t * 68 + c2 + 1] = h2pack(v.z, v.w);
    }
}

// ---------------------------------------------------------------------------
// Kernel 2: persistent; fp16 mma; GEMM1 re-tiled 2m x 4ni for operand reuse
// ---------------------------------------------------------------------------
__global__ __launch_bounds__(512, 1)
void moe_kernel(const float* __restrict__ x,
                const float* __restrict__ bd,
                const float* __restrict__ bs,
                float* __restrict__ out) {
    extern __shared__ u32 smu[];
    u32*   XA = smu + OFF_XA;
    u32*   KS = smu + OFF_KS;
    u32*   VT = smu + OFF_VT;
    u32*   PS = smu + OFF_PS;
    u32*   OS = smu + OFF_OS;
    u32*   O1 = smu + OFF_O1;
    u32*   WS = smu + OFF_WS;
    float* S  = (float*)(smu + OFF_OS);

    const u32 ws_s = (u32)__cvta_generic_to_shared(WS);

    const int tid  = threadIdx.x;
    const int lane = tid & 31;
    const int wid  = tid >> 5;
    const int g    = lane >> 2;
    const int tq   = lane & 3;

    // mappings
    const int matId = wid >> 3;
    const int kj    = wid & 7;
    // GEMM1 K-warps: m-pair (32 rows) x col-quad (32 cols)
    const int k_mp  = (kj & 1) * 32;
    const int k_nq  = (kj >> 1) * 32;      // col base (halfs)
    // GEMM1 V-warps: row-pair (32 V-rows) x t-quad (32 t)
    const int v_mp  = (kj >> 1) * 32;
    const int v_tq  = (kj & 1) * 32;
    const int h     = wid >> 3;
    const int a_m0  = (wid & 3) * 16;
    const int a_n0  = ((wid >> 2) & 1) * 32;
    const int g2_m0 = (wid & 3) * 16;
    const int g2_n0 = (wid >> 2) * 32;

    int tile = blockIdx.x;
    if (tile >= NTILES) return;
    int n = tile & 31;
    int b = tile >> 5;

    {
        const int e0 = d_eidx[b][0];
        const u32* wdsrc = WdT_g + (size_t)(e0 * 32 + n) * WDEXP;
        #pragma unroll
        for (int j = tid; j < WDEXP / 4; j += 512)
            cp16(ws_s + (u32)(j * 16), wdsrc + j * 4);
        CP_COMMIT();
    }
    load_x_tile(XA, x, b, n, tid);

    while (true) {
        const int  ntile   = tile + GRIDP;
        const bool hasNext = (ntile < NTILES);
        const int  nn = ntile & 31;
        const int  nb = ntile >> 5;

        float accv[4][4];
        #pragma unroll
        for (int ni = 0; ni < 4; ++ni)
            #pragma unroll
            for (int c = 0; c < 4; ++c) accv[ni][c] = 0.f;

        for (int slot = 0; slot < K_; ++slot) {
            const int   e  = d_eidx[b][slot];
            const float gg = d_gateg[b][slot];

            CP_WAIT0();
            __syncthreads();

            // ========== GEMM1 (re-tiled): K = x@W0+b0 ; V^T = W1^T@x^T + b1 ==========
            {
                float acc[2][4][4];
                if (matId == 0) {
                    const float* bm = bd + ((size_t)(e * 2 + 0) * N_ + n) * D_;
                    #pragma unroll
                    for (int ni = 0; ni < 4; ++ni) {
                        const int col = k_nq + 8 * ni + 2 * tq;
                        const float b0v = bm[col];
                        const float b1v = bm[col + 1];
                        #pragma unroll
                        for (int mt = 0; mt < 2; ++mt) {
                            acc[mt][ni][0] = b0v; acc[mt][ni][1] = b1v;
                            acc[mt][ni][2] = b0v; acc[mt][ni][3] = b1v;
                        }
                    }
                } else {
                    const float* bm = bd + ((size_t)(e * 2 + 1) * N_ + n) * D_;
                    #pragma unroll
                    for (int mt = 0; mt < 2; ++mt) {
                        const float blo = bm[v_mp + 16 * mt + g];
                        const float bhi = bm[v_mp + 16 * mt + 8 + g];
                        #pragma unroll
                        for (int ni = 0; ni < 4; ++ni) {
                            acc[mt][ni][0] = blo; acc[mt][ni][1] = blo;
                            acc[mt][ni][2] = bhi; acc[mt][ni][3] = bhi;
                        }
                    }
                }
                #pragma unroll
                for (int s = 0; s < 4; ++s) {
                    const u32* cur = WS + s * WBLK;
                    #pragma unroll
                    for (int kk = 0; kk < 2; ++kk) {
                        const int d2g = s * 16 + kk * 8;
                        const int w0  = (kk * 8 + tq) * 136;
                        const int w1  = (kk * 8 + tq + 4) * 136;
                        if (matId == 0) {
                            u32 a[2][4];
                            #pragma unroll
                            for (int mt = 0; mt < 2; ++mt) {
                                const int rb = k_mp + 16 * mt;
                                a[mt][0] = XA[(rb + g)     * 68 + d2g + tq];
                                a[mt][1] = XA[(rb + 8 + g) * 68 + d2g + tq];
                                a[mt][2] = XA[(rb + g)     * 68 + d2g + tq + 4];
                                a[mt][3] = XA[(rb + 8 + g) * 68 + d2g + tq + 4];
                            }
                            #pragma unroll
                            for (int ni = 0; ni < 4; ++ni) {
                                u32 bf[2];
                                bf[0] = cur[w0 + k_nq + 8 * ni + g];
                                bf[1] = cur[w1 + k_nq + 8 * ni + g];
                                mma_f16(acc[0][ni], a[0], bf);
                                mma_f16(acc[1][ni], a[1], bf);
                            }
                        } else {
                            const u32* cv = cur + WSLAB;
                            u32 a[2][4];
                            #pragma unroll
                            for (int mt = 0; mt < 2; ++mt) {
                                const int rb = v_mp + 16 * mt;
                                a[mt][0] = cv[w0 + rb + g];
                                a[mt][1] = cv[w0 + rb + 8 + g];
                                a[mt][2] = cv[w1 + rb + g];
                                a[mt][3] = cv[w1 + rb + 8 + g];
                            }
                            #pragma unroll
                            for (int ni = 0; ni < 4; ++ni) {
                                u32 bf[2];
                                bf[0] = XA[(v_tq + 8 * ni + g) * 68 + d2g + tq];
                                bf[1] = XA[(v_tq + 8 * ni + g) * 68 + d2g + tq + 4];
                                mma_f16(acc[0][ni], a[0], bf);
                                mma_f16(acc[1][ni], a[1], bf);
                            }
                        }
                    }
                }
                if (matId == 0) {
                    #pragma unroll
                    for (int mt = 0; mt < 2; ++mt)
                        #pragma unroll
                        for (int ni = 0; ni < 4; ++ni) {
                            const int r0 = k_mp + 16 * mt + g;
                            const int c2 = (k_nq >> 1) + 4 * ni + tq;
                            KS[r0 * 68 + c2]       = h2pack(acc[mt][ni][0], acc[mt][ni][1]);
                            KS[(r0 + 8) * 68 + c2] = h2pack(acc[mt][ni][2], acc[mt][ni][3]);
                        }
                } else {
                    #pragma unroll
                    for (int mt = 0; mt < 2; ++mt)
                        #pragma unroll
                        for (int ni = 0; ni < 4; ++ni) {
                            const int r0 = v_mp + 16 * mt + g;
                            const int c2 = (v_tq >> 1) + 4 * ni + tq;
                            VT[r0 * 36 + c2]       = h2pack(acc[mt][ni][0], acc[mt][ni][1]);
                            VT[(r0 + 8) * 36 + c2] = h2pack(acc[mt][ni][2], acc[mt][ni][3]);
                        }
                }
                __syncthreads();
            }

            // prefetch Ws0+Ws1 — hides behind att/softmax/PV
            {
                const u32* wssrc = WsT_g + (size_t)(e * 2) * 4 * WSLAB;
                #pragma unroll
                for (int j = tid; j < WDEXP / 4; j += 512)
                    cp16(ws_s + (u32)(j * 16), wssrc + j * 4);
                CP_COMMIT();
            }

            // ========== att: S = Q K^T / 8 (per head) ==========
            {
                const int hb2 = h * 32;
                float sa[4][4];
                #pragma unroll
                for (int ni = 0; ni < 4; ++ni)
                    #pragma unroll
                    for (int c = 0; c < 4; ++c) sa[ni][c] = 0.f;
                #pragma unroll
                for (int ks = 0; ks < 4; ++ks) {
                    const int d2g = hb2 + ks * 8;
                    u32 a[4];
                    a[0] = XA[(a_m0 + g)     * 68 + d2g + tq];
                    a[1] = XA[(a_m0 + 8 + g) * 68 + d2g + tq];
                    a[2] = XA[(a_m0 + g)     * 68 + d2g + tq + 4];
                    a[3] = XA[(a_m0 + 8 + g) * 68 + d2g + tq + 4];
                    #pragma unroll
                    for (int ni = 0; ni < 4; ++ni) {
                        u32 bf[2];
                        bf[0] = KS[(a_n0 + 8 * ni + g) * 68 + d2g + tq];
                        bf[1] = KS[(a_n0 + 8 * ni + g) * 68 + d2g + tq + 4];
                        mma_f16(sa[ni], a, bf);
                    }
                }
                float* Sh = S + h * 4352;
                #pragma unroll
                for (int ni = 0; ni < 4; ++ni) {
                    const int cc = a_n0 + 8 * ni + 2 * tq;
                    *(u64*)&Sh[(a_m0 + g)     * 68 + cc] = fpack(0.125f * sa[ni][0], 0.125f * sa[ni][1]);
                    *(u64*)&Sh[(a_m0 + 8 + g) * 68 + cc] = fpack(0.125f * sa[ni][2], 0.125f * sa[ni][3]);
                }
                __syncthreads();
            }

            // after att of slot 1, XA is dead: prefetch next tile's x
            if (slot == 1 && hasNext)
                load_x_tile(XA, x, nb, nn, tid);

            // ========== softmax -> P (half) ==========
            {
                __half* Pb = (__half*)PS;
                #pragma unroll
                for (int j = 0; j < 8; ++j) {
                    const int r  = wid * 8 + j;
                    const int hh = r >> 6;
                    const int t  = r & 63;
                    float* row = S + hh * 4352 + t * 68;
                    const float a0 = row[lane];
                    const float a1 = row[lane + 32];
                    float m = fmaxf(a0, a1);
                    #pragma unroll
                    for (int o = 16; o > 0; o >>= 1) m = fmaxf(m, __shfl_xor_sync(0xffffffffu, m, o));
                    const float e0 = __expf(a0 - m);
                    const float e1 = __expf(a1 - m);
                    float sum = e0 + e1;
                    #pragma unroll
                    for (int o = 16; o > 0; o >>= 1) sum += __shfl_xor_sync(0xffffffffu, sum, o);
                    const float inv = 1.0f / sum;
                    __half* Ph = Pb + hh * 4608 + t * 72;
                    Ph[lane]      = __float2half_rn(e0 * inv);
                    Ph[lane + 32] = __float2half_rn(e1 * inv);
                }
                __syncthreads();
            }

            // ========== O = P V (per head) ==========
            {
                const u32* Pu = PS + h * 2304;
                float oa[4][4];
                #pragma unroll
                for (int ni = 0; ni < 4; ++ni)
                    #pragma unroll
                    for (int c = 0; c < 4; ++c) oa[ni][c] = 0.f;
                #pragma unroll
                for (int ks = 0; ks < 4; ++ks) {
                    const int kt2 = ks * 8;
                    u32 a[4];
                    a[0] = Pu[(a_m0 + g)     * 36 + kt2 + tq];
                    a[1] = Pu[(a_m0 + 8 + g) * 36 + kt2 + tq];
                    a[2] = Pu[(a_m0 + g)     * 36 + kt2 + tq + 4];
                    a[3] = Pu[(a_m0 + 8 + g) * 36 + kt2 + tq + 4];
                    #pragma unroll
                    for (int ni = 0; ni < 4; ++ni) {
                        u32 bf[2];
                        bf[0] = VT[(h * 64 + a_n0 + 8 * ni + g) * 36 + kt2 + tq];
                        bf[1] = VT[(h * 64 + a_n0 + 8 * ni + g) * 36 + kt2 + tq + 4];
                        mma_f16(oa[ni], a, bf);
                    }
                }
                #pragma unroll
                for (int ni = 0; ni < 4; ++ni) {
                    const int c2 = h * 32 + a_n0 / 2 + 4 * ni + tq;
                    OS[(a_m0 + g)     * 68 + c2] = h2pack(oa[ni][0], oa[ni][1]);
                    OS[(a_m0 + 8 + g) * 68 + c2] = h2pack(oa[ni][2], oa[ni][3]);
                }
                CP_WAIT0();
                __syncthreads();
            }

            // ========== GEMM2: O1 = relu(O @ Ws0 + bs0) ==========
            {
                const float* bsp = bs + (e * 2 + 0) * D_;
                float acc[4][4];
                #pragma unroll
                for (int ni = 0; ni < 4; ++ni) {
                    const float b0v = bsp[g2_n0 + 8 * ni + 2 * tq];
                    const float b1v = bsp[g2_n0 + 8 * ni + 2 * tq + 1];
                    acc[ni][0] = b0v; acc[ni][1] = b1v; acc[ni][2] = b0v; acc[ni][3] = b1v;
                }
                #pragma unroll
                for (int s = 0; s < 4; ++s) {
                    const u32* cur = WS + s * WSLAB;
                    #pragma unroll
                    for (int kk = 0; kk < 2; ++kk) {
                        const int d2g = s * 16 + kk * 8;
                        const int w0  = (kk * 8 + tq) * 136;
                        const int w1  = (kk * 8 + tq + 4) * 136;
                        u32 a[4];
                        a[0] = OS[(g2_m0 + g)     * 68 + d2g + tq];
                        a[1] = OS[(g2_m0 + 8 + g) * 68 + d2g + tq];
                        a[2] = OS[(g2_m0 + g)     * 68 + d2g + tq + 4];
                        a[3] = OS[(g2_m0 + 8 + g) * 68 + d2g + tq + 4];
                        #pragma unroll
                        for (int ni = 0; ni < 4; ++ni) {
                            u32 bf[2];
                            bf[0] = cur[w0 + g2_n0 + 8 * ni + g];
                            bf[1] = cur[w1 + g2_n0 + 8 * ni + g];
                            mma_f16(acc[ni], a, bf);
                        }
                    }
                }
                #pragma unroll
                for (int ni = 0; ni < 4; ++ni) {
                    const int c2 = g2_n0 / 2 + 4 * ni + tq;
                    O1[(g2_m0 + g)     * 68 + c2] = h2pack(fmaxf(acc[ni][0], 0.f), fmaxf(acc[ni][1], 0.f));
                    O1[(g2_m0 + 8 + g) * 68 + c2] = h2pack(fmaxf(acc[ni][2], 0.f), fmaxf(acc[ni][3], 0.f));
                }
                __syncthreads();
            }

            // ========== GEMM3: out_e = O1 @ Ws1 + bs1 ; accv += g*exp ==========
            {
                const float* bsp = bs + (e * 2 + 1) * D_;
                float acc[4][4];
                #pragma unroll
                for (int ni = 0; ni < 4; ++ni) {
                    const float b0v = bsp[g2_n0 + 8 * ni + 2 * tq];
                    const float b1v = bsp[g2_n0 + 8 * ni + 2 * tq + 1];
                    acc[ni][0] = b0v; acc[ni][1] = b1v; acc[ni][2] = b0v; acc[ni][3] = b1v;
                }
                #pragma unroll
                for (int s = 0; s < 4; ++s) {
                    const u32* cur = WS + 4 * WSLAB + s * WSLAB;
                    #pragma unroll
                    for (int kk = 0; kk < 2; ++kk) {
                        const int d2g = s * 16 + kk * 8;
                        const int w0  = (kk * 8 + tq) * 136;
                        const int w1  = (kk * 8 + tq + 4) * 136;
                        u32 a[4];
                        a[0] = O1[(g2_m0 + g)     * 68 + d2g + tq];
                        a[1] = O1[(g2_m0 + 8 + g) * 68 + d2g + tq];
                        a[2] = O1[(g2_m0 + g)     * 68 + d2g + tq + 4];
                        a[3] = O1[(g2_m0 + 8 + g) * 68 + d2g + tq + 4];
                        #pragma unroll
                        for (int ni = 0; ni < 4; ++ni) {
                            u32 bf[2];
                            bf[0] = cur[w0 + g2_n0 + 8 * ni + g];
                            bf[1] = cur[w1 + g2_n0 + 8 * ni + g];
                            mma_f16(acc[ni], a, bf);
                        }
                    }
                }
                #pragma unroll
                for (int ni = 0; ni < 4; ++ni)
                    #pragma unroll
                    for (int c = 0; c < 4; ++c)
                        accv[ni][c] += gg * __expf(acc[ni][c]);
                __syncthreads();
            }

            // stage next weights: e1 (slot 0) or next tile's e0 (slot 1)
            if (slot == 0) {
                const int e1 = d_eidx[b][1];
                const u32* wdsrc = WdT_g + (size_t)(e1 * 32 + n) * WDEXP;
                #pragma unroll
                for (int j = tid; j < WDEXP / 4; j += 512)
                    cp16(ws_s + (u32)(j * 16), wdsrc + j * 4);
                CP_COMMIT();
            } else if (hasNext) {
                const int e0n = d_eidx[nb][0];
                const u32* wdsrc = WdT_g + (size_t)(e0n * 32 + nn) * WDEXP;
                #pragma unroll
                for (int j = tid; j < WDEXP / 4; j += 512)
                    cp16(ws_s + (u32)(j * 16), wdsrc + j * 4);
                CP_COMMIT();
            }
        }

        // ---- combine epilogue for this tile ----
        const float EPSF = 2.2204460492503131e-16f;
        #pragma unroll
        for (int ni = 0; ni < 4; ++ni) {
            const int cc  = g2_n0 + 8 * ni + 2 * tq;
            const int t0r = g2_m0 + g;
            const int t1r = g2_m0 + 8 + g;
            float v0 = accv[ni][0]; if (v0 == 0.f) v0 = EPSF;
            float v1 = accv[ni][1]; if (v1 == 0.f) v1 = EPSF;
            float v2 = accv[ni][2]; if (v2 == 0.f) v2 = EPSF;
            float v3 = accv[ni][3]; if (v3 == 0.f) v3 = EPSF;
            *(u64*)&out[(((size_t)b * T_ + t0r) * N_ + n) * D_ + cc] = fpack(__logf(v0), __logf(v1));
            *(u64*)&out[(((size_t)b * T_ + t1r) * N_ + n) * D_ + cc] = fpack(__logf(v2), __logf(v3));
        }

        if (!hasNext) break;
        tile = ntile; n = nn; b = nb;
    }
}

// ---------------------------------------------------------------------------
// launcher
// ---------------------------------------------------------------------------
extern "C" void kernel_launch(void* const* d_in, const int* in_sizes, int n_in,
                              void* d_out, int out_size) {
    const float* x  = (const float*)d_in[0];
    const float* Wg = (const float*)d_in[1];
    const float* Wd = (const float*)d_in[2];
    const float* bd = (const float*)d_in[3];
    const float* Ws = (const float*)d_in[4];
    const float* bs = (const float*)d_in[5];
    float* out = (float*)d_out;

    const int smem_bytes = SMEM_U * 4; // 176128 B
    cudaFuncSetAttribute(moe_kernel, cudaFuncAttributeMaxDynamicSharedMemorySize, smem_bytes);

    prep_gate_kernel<<<3136, 512>>>(Wd, Ws, x);
    gate_kernel<<<B_, 128>>>(Wg);
    moe_kernel<<<GRIDP, 512, smem_bytes>>>(x, bd, bs, out);
}